// round 2
// baseline (speedup 1.0000x reference)
#include <cuda_runtime.h>
#include <math.h>

// ---------------- problem dims ----------------
// B=8 S=32 P=64 D=256 H=1024 K=1024 OBS=64 CTX=4 NH=4 dh=64
// rows: BS=256, BSP=16384, BSP*CTX=65536

// ---------------- scratch (static device memory; no allocs allowed) --------
__device__ float g_obsproj[256 * 256];        // (B*S, D)
__device__ float g_x0[16384 * 256];           // SA input tokens
__device__ float g_qkv[65536 * 768];          // shared qkv scratch (max size)
__device__ float g_attn[65536 * 256];         // attention output scratch
__device__ float g_proj[65536 * 256];         // projection scratch
__device__ float g_tok[16384 * 256];          // tokens after SA+LN
__device__ float g_xctx[65536 * 256];         // context transformer activations
__device__ float g_hid[65536 * 1024];         // FFN hidden / VQ scores / dec h2
__device__ float g_xlast[16384 * 256];        // layer-2 last-position branch
__device__ float g_cur[16384 * 256];          // cur = x[:, -1]
__device__ float g_ctxtok[16384 * 256];       // delta-scan outputs
__device__ float g_acat[512 * 512];           // concat([c, c-prev]) per scan step
__device__ float g_dtmp[512 * 256];           // scan step gemm output
__device__ float g_cn[1024];                  // codebook row norms
__device__ float g_red[256];                  // reduction partials
__device__ int   g_idx[16384];                // VQ indices

// ---------------- generic fp32 NT gemm: C = A @ W^T (+bias)(+relu) --------
// A: M x K row-major, W: N x K row-major. All M,N multiples of 64; K of 16.
// Optional Arows: row gather for A (used for codebook[idx] in decoder).
__global__ void gemm_nt(const float* __restrict__ A, const float* __restrict__ W,
                        const float* __restrict__ bias, float* __restrict__ C,
                        int M, int N, int K, int relu, const int* __restrict__ Arows)
{
    __shared__ float As[16][64];
    __shared__ float Ws[16][64];
    const int tid = threadIdx.x;
    const int rowTile = blockIdx.y * 64;
    const int colTile = blockIdx.x * 64;
    const int lr = tid >> 2;          // 0..63 tile row for loading
    const int lc = (tid & 3) << 2;    // k offset 0,4,8,12
    const int tr = (tid >> 4) << 2;   // micro-tile row base
    const int tc = (tid & 15) << 2;   // micro-tile col base

    int am = rowTile + lr;
    if (Arows) am = Arows[am];
    const float* Aptr = A + (size_t)am * K + lc;
    const float* Wptr = W + (size_t)(colTile + lr) * K + lc;

    float acc[4][4] = {};
    for (int k0 = 0; k0 < K; k0 += 16) {
        float4 av = *reinterpret_cast<const float4*>(Aptr + k0);
        float4 wv = *reinterpret_cast<const float4*>(Wptr + k0);
        As[lc + 0][lr] = av.x; As[lc + 1][lr] = av.y;
        As[lc + 2][lr] = av.z; As[lc + 3][lr] = av.w;
        Ws[lc + 0][lr] = wv.x; Ws[lc + 1][lr] = wv.y;
        Ws[lc + 2][lr] = wv.z; Ws[lc + 3][lr] = wv.w;
        __syncthreads();
#pragma unroll
        for (int k = 0; k < 16; k++) {
            float4 a = *reinterpret_cast<const float4*>(&As[k][tr]);
            float4 b = *reinterpret_cast<const float4*>(&Ws[k][tc]);
            acc[0][0] += a.x * b.x; acc[0][1] += a.x * b.y; acc[0][2] += a.x * b.z; acc[0][3] += a.x * b.w;
            acc[1][0] += a.y * b.x; acc[1][1] += a.y * b.y; acc[1][2] += a.y * b.z; acc[1][3] += a.y * b.w;
            acc[2][0] += a.z * b.x; acc[2][1] += a.z * b.y; acc[2][2] += a.z * b.z; acc[2][3] += a.z * b.w;
            acc[3][0] += a.w * b.x; acc[3][1] += a.w * b.y; acc[3][2] += a.w * b.z; acc[3][3] += a.w * b.w;
        }
        __syncthreads();
    }
#pragma unroll
    for (int i = 0; i < 4; i++) {
#pragma unroll
        for (int j = 0; j < 4; j++) {
            float v = acc[i][j];
            if (bias) v += bias[colTile + tc + j];
            if (relu) v = fmaxf(v, 0.0f);
            C[(size_t)(rowTile + tr + i) * N + colTile + tc + j] = v;
        }
    }
}

// ---------------- patch proj expand: x0 = obsproj[bs] + pos_embed[p] ------
__global__ void expand_tok(const float* __restrict__ op, const float* __restrict__ pe,
                           float* __restrict__ x0)
{
    size_t i = (size_t)blockIdx.x * blockDim.x + threadIdx.x;  // 16384*256
    int d = (int)(i & 255);
    int row = (int)(i >> 8);
    int p = row & 63;
    int bs = row >> 6;
    x0[i] = op[bs * 256 + d] + pe[p * 256 + d];
}

// ---------------- self-attention (seq=64, dh=64), one block per (n,h) -----
// XOR swizzle makes transposed K/V tile stores AND reads conflict-free.
__global__ void sa_attn(const float* __restrict__ qkv, float* __restrict__ out)
{
    __shared__ float qs[64][64];
    __shared__ float kt[64][64];   // swizzled: kt[d][(l+d)&63] = k[l][d]
    __shared__ float ss[64][64];   // swizzled: ss[r][(c+r)&63]
    int n = blockIdx.x, h = blockIdx.y;
    int tid = threadIdx.x;
    const float* base = qkv + (size_t)n * 64 * 768 + h * 64;
#pragma unroll
    for (int i = 0; i < 16; i++) {
        int e = tid + i * 256, l = e >> 6, d = e & 63;
        qs[l][d] = base[l * 768 + d];
        kt[d][(l + d) & 63] = base[l * 768 + 256 + d];
    }
    __syncthreads();
#pragma unroll
    for (int i = 0; i < 16; i++) {
        int e = tid + i * 256, r = e >> 6, c = e & 63;
        float acc = 0.0f;
#pragma unroll
        for (int d = 0; d < 64; d++) acc += qs[r][d] * kt[d][(c + d) & 63];
        ss[r][(c + r) & 63] = acc * 0.125f;
    }
    __syncthreads();
    // V load (overwrites kt, already consumed) runs alongside softmax
#pragma unroll
    for (int i = 0; i < 16; i++) {
        int e = tid + i * 256, l = e >> 6, d = e & 63;
        kt[d][(l + d) & 63] = base[l * 768 + 512 + d];
    }
    if (tid < 64) {
        int r = tid;
        float mx = -1e30f;
        for (int j = 0; j < 64; j++) mx = fmaxf(mx, ss[r][(j + r) & 63]);
        float sum = 0.0f;
        for (int j = 0; j < 64; j++) {
            float e = expf(ss[r][(j + r) & 63] - mx);
            ss[r][(j + r) & 63] = e; sum += e;
        }
        float inv = 1.0f / sum;
        for (int j = 0; j < 64; j++) ss[r][(j + r) & 63] *= inv;
    }
    __syncthreads();
#pragma unroll
    for (int i = 0; i < 16; i++) {
        int e = tid + i * 256, r = e >> 6, c = e & 63;
        float acc = 0.0f;
#pragma unroll
        for (int j = 0; j < 64; j++) acc += ss[r][(j + r) & 63] * kt[c][(j + c) & 63];
        out[((size_t)n * 64 + r) * 256 + h * 64 + c] = acc;
    }
}

// ---------------- fused residual LayerNorm, warp per row, D=256 -----------
__global__ void ln_res(const float* __restrict__ x1, int ld1,
                       const float* __restrict__ x2,
                       const float* __restrict__ g, const float* __restrict__ b,
                       float* __restrict__ out, int M)
{
    int gw = (int)((blockIdx.x * (size_t)blockDim.x + threadIdx.x) >> 5);
    int lane = threadIdx.x & 31;
    if (gw >= M) return;
    const float* r1 = x1 + (size_t)gw * ld1;
    const float* r2 = x2 ? x2 + (size_t)gw * 256 : nullptr;
    float v[8];
    float s = 0.0f;
#pragma unroll
    for (int i = 0; i < 8; i++) {
        float t = r1[lane + i * 32];
        if (r2) t += r2[lane + i * 32];
        v[i] = t; s += t;
    }
#pragma unroll
    for (int o = 16; o; o >>= 1) s += __shfl_xor_sync(0xffffffffu, s, o);
    float mean = s * (1.0f / 256.0f);
    float var = 0.0f;
#pragma unroll
    for (int i = 0; i < 8; i++) { float d = v[i] - mean; var += d * d; }
#pragma unroll
    for (int o = 16; o; o >>= 1) var += __shfl_xor_sync(0xffffffffu, var, o);
    float rstd = rsqrtf(var * (1.0f / 256.0f) + 1e-5f);
    float* orow = out + (size_t)gw * 256;
#pragma unroll
    for (int i = 0; i < 8; i++) {
        int d = lane + i * 32;
        orow[d] = (v[i] - mean) * rstd * g[d] + b[d];
    }
}

// ---------------- windowed context gather (CTX=4, zero-masked) ------------
__global__ void window_gather(const float* __restrict__ tok, float* __restrict__ x)
{
    size_t i = (size_t)blockIdx.x * blockDim.x + threadIdx.x;  // 65536*256
    int d = (int)(i & 255);
    int row = (int)(i >> 8);
    int c = row & 3;
    int seq = row >> 2;              // (b*32+s)*64+p
    int p = seq & 63;
    int bs = seq >> 6;
    int s = bs & 31;
    int b = bs >> 5;
    int sp = s + c - 3;
    x[i] = (sp < 0) ? 0.0f : tok[(((size_t)(b * 32 + sp) * 64 + p) << 8) + d];
}

// ---------------- context attention (CTX=4, dh=64), warp per (seq,h) ------
__global__ void ctx_attn(const float* __restrict__ qkv, float* __restrict__ out,
                         int last_only)
{
    int gw = (int)((blockIdx.x * (size_t)blockDim.x + threadIdx.x) >> 5);
    int lane = threadIdx.x & 31;
    int seq = gw >> 2, h = gw & 3;
    if (seq >= 16384) return;
    const float* base = qkv + (size_t)seq * 4 * 768 + h * 64;
    float k[4][2], v[4][2];
#pragma unroll
    for (int c = 0; c < 4; c++) {
        k[c][0] = base[c * 768 + 256 + lane];  k[c][1] = base[c * 768 + 256 + lane + 32];
        v[c][0] = base[c * 768 + 512 + lane];  v[c][1] = base[c * 768 + 512 + lane + 32];
    }
    if (last_only) {
        float q0 = base[3 * 768 + lane], q1 = base[3 * 768 + lane + 32];
        float p[4];
#pragma unroll
        for (int j = 0; j < 4; j++) {
            float s = q0 * k[j][0] + q1 * k[j][1];
#pragma unroll
            for (int o = 16; o; o >>= 1) s += __shfl_xor_sync(0xffffffffu, s, o);
            p[j] = s * 0.125f;
        }
        float mx = fmaxf(fmaxf(p[0], p[1]), fmaxf(p[2], p[3]));
        float e0 = expf(p[0] - mx), e1 = expf(p[1] - mx), e2 = expf(p[2] - mx), e3 = expf(p[3] - mx);
        float inv = 1.0f / (e0 + e1 + e2 + e3);
        p[0] = e0 * inv; p[1] = e1 * inv; p[2] = e2 * inv; p[3] = e3 * inv;
        float o0 = p[0] * v[0][0] + p[1] * v[1][0] + p[2] * v[2][0] + p[3] * v[3][0];
        float o1 = p[0] * v[0][1] + p[1] * v[1][1] + p[2] * v[2][1] + p[3] * v[3][1];
        out[(size_t)seq * 256 + h * 64 + lane] = o0;
        out[(size_t)seq * 256 + h * 64 + lane + 32] = o1;
    } else {
        float q[4][2];
#pragma unroll
        for (int c = 0; c < 4; c++) {
            q[c][0] = base[c * 768 + lane]; q[c][1] = base[c * 768 + lane + 32];
        }
        float p[4][4];
#pragma unroll
        for (int i = 0; i < 4; i++) {
#pragma unroll
            for (int j = 0; j < 4; j++) {
                float s = q[i][0] * k[j][0] + q[i][1] * k[j][1];
#pragma unroll
                for (int o = 16; o; o >>= 1) s += __shfl_xor_sync(0xffffffffu, s, o);
                p[i][j] = s * 0.125f;
            }
            float mx = fmaxf(fmaxf(p[i][0], p[i][1]), fmaxf(p[i][2], p[i][3]));
            float e0 = expf(p[i][0] - mx), e1 = expf(p[i][1] - mx);
            float e2 = expf(p[i][2] - mx), e3 = expf(p[i][3] - mx);
            float inv = 1.0f / (e0 + e1 + e2 + e3);
            p[i][0] = e0 * inv; p[i][1] = e1 * inv; p[i][2] = e2 * inv; p[i][3] = e3 * inv;
        }
#pragma unroll
        for (int i = 0; i < 4; i++) {
            float o0 = p[i][0] * v[0][0] + p[i][1] * v[1][0] + p[i][2] * v[2][0] + p[i][3] * v[3][0];
            float o1 = p[i][0] * v[0][1] + p[i][1] * v[1][1] + p[i][2] * v[2][1] + p[i][3] * v[3][1];
            size_t row = (size_t)seq * 4 + i;
            out[row * 256 + h * 64 + lane] = o0;
            out[row * 256 + h * 64 + lane + 32] = o1;
        }
    }
}

// ---------------- delta scan helpers --------------------------------------
__global__ void copy_out0(const float* __restrict__ cur, float* __restrict__ ct)
{
    int i = blockIdx.x * blockDim.x + threadIdx.x;  // 512*256
    int d = i & 255; int m = i >> 8;                // m = b*64+p
    int b = m >> 6, p = m & 63;
    size_t r = ((size_t)b * 2048 + p) * 256 + d;    // rows (b, s=0, p)
    ct[r] = cur[r];
}

__global__ void build_acat(const float* __restrict__ cur, const float* __restrict__ ct,
                           float* __restrict__ acat, int s)
{
    int i = blockIdx.x * blockDim.x + threadIdx.x;  // 512*512
    int kk = i & 511; int m = i >> 9;
    int b = m >> 6, p = m & 63;
    size_t g = (size_t)b * 2048 + s * 64 + p;
    float v;
    if (kk < 256) v = cur[g * 256 + kk];
    else          v = cur[g * 256 + kk - 256] - ct[(g - 64) * 256 + kk - 256];
    acat[i] = v;
}

__global__ void scatter_delta(const float* __restrict__ dtmp, float* __restrict__ ct, int s)
{
    int i = blockIdx.x * blockDim.x + threadIdx.x;  // 512*256
    int d = i & 255; int m = i >> 8;
    int b = m >> 6, p = m & 63;
    ct[((size_t)b * 2048 + s * 64 + p) * 256 + d] = dtmp[i];
}

// ---------------- VQ ------------------------------------------------------
__global__ void cb_norms(const float* __restrict__ cb, float* __restrict__ cn)
{
    int gw = (int)((blockIdx.x * (size_t)blockDim.x + threadIdx.x) >> 5);
    int lane = threadIdx.x & 31;
    if (gw >= 1024) return;
    const float* r = cb + (size_t)gw * 256;
    float s = 0.0f;
#pragma unroll
    for (int i = 0; i < 8; i++) { float v = r[lane + i * 32]; s += v * v; }
#pragma unroll
    for (int o = 16; o; o >>= 1) s += __shfl_xor_sync(0xffffffffu, s, o);
    if (!lane) cn[gw] = s;
}

// Mirrors jax: dist = (||x||^2 - 2*score) + ||c||^2, argmin, lowest-index ties.
__global__ void vq_argmin(const float* __restrict__ x, const float* __restrict__ scores,
                          const float* __restrict__ cn, int* __restrict__ idx)
{
    int gw = (int)((blockIdx.x * (size_t)blockDim.x + threadIdx.x) >> 5);
    int lane = threadIdx.x & 31;
    if (gw >= 16384) return;
    const float* xr = x + (size_t)gw * 256;
    float xx = 0.0f;
#pragma unroll
    for (int i = 0; i < 8; i++) { float v = xr[lane + i * 32]; xx += v * v; }
#pragma unroll
    for (int o = 16; o; o >>= 1) xx += __shfl_xor_sync(0xffffffffu, xx, o);
    const float* sr = scores + (size_t)gw * 1024;
    float best = 3.4e38f; int bi = 0x7fffffff;
    for (int j = lane; j < 1024; j += 32) {
        float d = (xx - 2.0f * sr[j]) + cn[j];
        if (d < best || (d == best && j < bi)) { best = d; bi = j; }
    }
#pragma unroll
    for (int o = 16; o; o >>= 1) {
        float ob = __shfl_xor_sync(0xffffffffu, best, o);
        int   oi = __shfl_xor_sync(0xffffffffu, bi, o);
        if (ob < best || (ob == best && oi < bi)) { best = ob; bi = oi; }
    }
    if (!lane) idx[gw] = bi;
}

// ---------------- deterministic MSE reduction ------------------------------
__global__ void mse_partial(const float* __restrict__ x, const float* __restrict__ cb,
                            const int* __restrict__ idx, float* __restrict__ red)
{
    __shared__ float sm[256];
    float s = 0.0f;
    size_t stride = (size_t)gridDim.x * blockDim.x;
    for (size_t i = (size_t)blockIdx.x * blockDim.x + threadIdx.x;
         i < (size_t)16384 * 256; i += stride) {
        int row = (int)(i >> 8), d = (int)(i & 255);
        float diff = x[i] - cb[(size_t)idx[row] * 256 + d];
        s += diff * diff;
    }
    sm[threadIdx.x] = s; __syncthreads();
    for (int o = 128; o; o >>= 1) {
        if ((int)threadIdx.x < o) sm[threadIdx.x] += sm[threadIdx.x + o];
        __syncthreads();
    }
    if (!threadIdx.x) red[blockIdx.x] = sm[0];
}

__global__ void mse_final(const float* __restrict__ red, float* __restrict__ out)
{
    __shared__ float sm[256];
    sm[threadIdx.x] = red[threadIdx.x]; __syncthreads();
    for (int o = 128; o; o >>= 1) {
        if ((int)threadIdx.x < o) sm[threadIdx.x] += sm[threadIdx.x + o];
        __syncthreads();
    }
    if (!threadIdx.x) {
        float mse = sm[0] / 4194304.0f;
        out[1064960] = 0.25f * mse;   // commit
        out[1064961] = mse;           // cb_loss
        out[1064962] = 1.25f * mse;   // total
    }
}

__global__ void idx_write(const int* __restrict__ idx, float* __restrict__ out)
{
    int i = blockIdx.x * blockDim.x + threadIdx.x;
    if (i < 16384) out[1048576 + i] = (float)idx[i];
}

// ---------------- host orchestration --------------------------------------
static inline float* sym(const void* s)
{
    void* p = nullptr;
    cudaGetSymbolAddress(&p, s);
    return (float*)p;
}

extern "C" void kernel_launch(void* const* d_in, const int* in_sizes, int n_in,
                              void* d_out, int out_size)
{
    (void)in_sizes; (void)n_in; (void)out_size;
    const float* obs      = (const float*)d_in[0];
    const float* patch_w  = (const float*)d_in[2];
    const float* patch_b  = (const float*)d_in[3];
    const float* pos_emb  = (const float*)d_in[4];
    const float* sa_qkv_w = (const float*)d_in[5];
    const float* sa_qkv_b = (const float*)d_in[6];
    const float* sa_out_w = (const float*)d_in[7];
    const float* sa_out_b = (const float*)d_in[8];
    const float* sa_ln_g  = (const float*)d_in[9];
    const float* sa_ln_b  = (const float*)d_in[10];
    const float* cqkv_w   = (const float*)d_in[11];
    const float* cqkv_b   = (const float*)d_in[12];
    const float* cout_w   = (const float*)d_in[13];
    const float* cout_b   = (const float*)d_in[14];
    const float* cff1_w   = (const float*)d_in[15];
    const float* cff1_b   = (const float*)d_in[16];
    const float* cff2_w   = (const float*)d_in[17];
    const float* cff2_b   = (const float*)d_in[18];
    const float* cln1_g   = (const float*)d_in[19];
    const float* cln1_b   = (const float*)d_in[20];
    const float* cln2_g   = (const float*)d_in[21];
    const float* cln2_b   = (const float*)d_in[22];
    const float* delta_w  = (const float*)d_in[23];
    const float* delta_b  = (const float*)d_in[24];
    const float* codebook = (const float*)d_in[25];
    const float* dec_w1   = (const float*)d_in[26];
    const float* dec_b1   = (const float*)d_in[27];
    const float* dec_w2   = (const float*)d_in[28];
    const float* dec_b2   = (const float*)d_in[29];
    const float* dec_w3   = (const float*)d_in[30];
    const float* dec_b3   = (const float*)d_in[31];
    float* out = (float*)d_out;

    float* obsproj = sym(g_obsproj);
    float* x0      = sym(g_x0);
    float* qkv     = sym(g_qkv);
    float* attn    = sym(g_attn);
    float* proj    = sym(g_proj);
    float* tok     = sym(g_tok);
    float* xctx    = sym(g_xctx);
    float* hid     = sym(g_hid);
    float* xlast   = sym(g_xlast);
    float* cur     = sym(g_cur);
    float* ctxtok  = sym(g_ctxtok);
    float* acat    = sym(g_acat);
    float* dtmp    = sym(g_dtmp);
    float* cn      = sym(g_cn);
    float* red     = sym(g_red);
    int*   vidx    = (int*)sym(g_idx);

    const int T = 256;

    // 1) patch projection + positional embed
    gemm_nt<<<dim3(4, 4), T>>>(obs, patch_w, patch_b, obsproj, 256, 256, 64, 0, nullptr);
    expand_tok<<<16384, T>>>(obsproj, pos_emb, x0);

    // 2) self-attention block over P=64
    gemm_nt<<<dim3(12, 256), T>>>(x0, sa_qkv_w, sa_qkv_b, qkv, 16384, 768, 256, 0, nullptr);
    sa_attn<<<dim3(256, 4), T>>>(qkv, attn);
    gemm_nt<<<dim3(4, 256), T>>>(attn, sa_out_w, sa_out_b, proj, 16384, 256, 256, 0, nullptr);
    ln_res<<<2048, T>>>(proj, 256, x0, sa_ln_g, sa_ln_b, tok, 16384);

    // 3) windowed context gather -> (16384 seqs, CTX=4, 256)
    window_gather<<<65536, T>>>(tok, xctx);

    // 4) context layer 0 (full)
    gemm_nt<<<dim3(12, 1024), T>>>(xctx, cqkv_w, cqkv_b, qkv, 65536, 768, 256, 0, nullptr);
    ctx_attn<<<8192, T>>>(qkv, attn, 0);
    gemm_nt<<<dim3(4, 1024), T>>>(attn, cout_w, cout_b, proj, 65536, 256, 256, 0, nullptr);
    ln_res<<<8192, T>>>(xctx, 256, proj, cln1_g, cln1_b, xctx, 65536);
    gemm_nt<<<dim3(16, 1024), T>>>(xctx, cff1_w, cff1_b, hid, 65536, 1024, 256, 1, nullptr);
    gemm_nt<<<dim3(4, 1024), T>>>(hid, cff2_w, cff2_b, proj, 65536, 256, 1024, 0, nullptr);
    ln_res<<<8192, T>>>(xctx, 256, proj, cln2_g, cln2_b, xctx, 65536);

    // 5) context layer 1 — only the last position (c=3) is consumed downstream
    gemm_nt<<<dim3(12, 1024), T>>>(xctx, cqkv_w + 196608, cqkv_b + 768, qkv,
                                   65536, 768, 256, 0, nullptr);
    ctx_attn<<<8192, T>>>(qkv, attn, 1);
    gemm_nt<<<dim3(4, 256), T>>>(attn, cout_w + 65536, cout_b + 256, proj,
                                 16384, 256, 256, 0, nullptr);
    ln_res<<<2048, T>>>(xctx + 768, 1024, proj, cln1_g + 256, cln1_b + 256, xlast, 16384);
    gemm_nt<<<dim3(16, 256), T>>>(xlast, cff1_w + 262144, cff1_b + 1024, hid,
                                  16384, 1024, 256, 1, nullptr);
    gemm_nt<<<dim3(4, 256), T>>>(hid, cff2_w + 262144, cff2_b + 256, proj,
                                 16384, 256, 1024, 0, nullptr);
    ln_res<<<2048, T>>>(xlast, 256, proj, cln2_g + 256, cln2_b + 256, cur, 16384);

    // 6) sequential delta scan over S
    copy_out0<<<512, T>>>(cur, ctxtok);
    for (int s = 1; s < 32; s++) {
        build_acat<<<1024, T>>>(cur, ctxtok, acat, s);
        gemm_nt<<<dim3(4, 8), T>>>(acat, delta_w, delta_b, dtmp, 512, 256, 512, 0, nullptr);
        scatter_delta<<<512, T>>>(dtmp, ctxtok, s);
    }

    // 7) VQ: scores = ctxtok @ codebook^T, then argmin (jax-matching dist)
    cb_norms<<<128, T>>>(codebook, cn);
    gemm_nt<<<dim3(16, 256), T>>>(ctxtok, codebook, nullptr, hid, 16384, 1024, 256, 0, nullptr);
    vq_argmin<<<2048, T>>>(ctxtok, hid, cn, vidx);

    // 8) losses (deterministic two-stage reduce)
    mse_partial<<<256, T>>>(ctxtok, codebook, vidx, red);
    mse_final<<<1, T>>>(red, out);
    idx_write<<<64, T>>>(vidx, out);

    // 9) decoder (input = codebook[idx], gathered inside gemm)
    gemm_nt<<<dim3(16, 256), T>>>(codebook, dec_w1, dec_b1, qkv, 16384, 1024, 256, 1, vidx);
    gemm_nt<<<dim3(16, 256), T>>>(qkv, dec_w2, dec_b2, hid, 16384, 1024, 1024, 1, nullptr);
    gemm_nt<<<dim3(1, 256), T>>>(hid, dec_w3, dec_b3, out, 16384, 64, 1024, 0, nullptr);
}

// round 6
// speedup vs baseline: 2.1293x; 2.1293x over previous
#include <cuda_runtime.h>
#include <cuda_bf16.h>
#include <math.h>

// B=8 S=32 P=64 D=256 H=1024 K=1024 OBS=64 CTX=4 NH=4 dh=64
// rows: BS=256, BSP=16384, BSP*CTX=65536

// ---------------- scratch ----------------
__device__ float g_obsproj[256 * 256];
__device__ float g_x0[16384 * 256];
__device__ float g_qkv[65536 * 768];
__device__ float g_proj[65536 * 256];
__device__ float g_tok[16384 * 256];
__device__ float g_xctx[65536 * 256];
__device__ float g_hid[16384 * 1024];        // VQ scores
__device__ float g_xlast[16384 * 256];
__device__ float g_cur[16384 * 256];
__device__ float g_ctxtok[16384 * 256];
__device__ float g_cn[1024];
__device__ float g_red[256];
__device__ int   g_idx[16384];

// bf16 hi/lo activation buffers
__device__ __nv_bfloat16 g_x0h[16384 * 256],  g_x0l[16384 * 256];
__device__ __nv_bfloat16 g_ath[65536 * 256],  g_atl[65536 * 256];
__device__ __nv_bfloat16 g_xh [65536 * 256],  g_xl [65536 * 256];
__device__ __nv_bfloat16 g_hh [65536 * 1024], g_hl [65536 * 1024];
__device__ __nv_bfloat16 g_xlh[16384 * 256],  g_xll[16384 * 256];
__device__ __nv_bfloat16 g_cth[16384 * 256],  g_ctl[16384 * 256];
__device__ __nv_bfloat16 g_wh [3538944],      g_wl [3538944];

// weight pool offsets (elements)
#define OFF_SAQKV 0
#define OFF_SAOUT 196608
#define OFF_CQKV0 262144
#define OFF_CQKV1 458752
#define OFF_COUT0 655360
#define OFF_COUT1 720896
#define OFF_FF1_0 786432
#define OFF_FF1_1 1048576
#define OFF_FF2_0 1310720
#define OFF_FF2_1 1572864
#define OFF_CB    1835008
#define OFF_D1    2097152
#define OFF_D2    2359296
#define OFF_D3    3407872

// ---------------- PTX helpers ----------------
__device__ __forceinline__ unsigned smem_u32(const void* p) {
    unsigned a;
    asm("{ .reg .u64 t; cvta.to.shared.u64 t, %1; cvt.u32.u64 %0, t; }"
        : "=r"(a) : "l"(p));
    return a;
}
__device__ __forceinline__ void cpa16(unsigned s, const void* g) {
    asm volatile("cp.async.cg.shared.global [%0], [%1], 16;"
                 :: "r"(s), "l"(g) : "memory");
}
__device__ __forceinline__ void cp_commit() {
    asm volatile("cp.async.commit_group;" ::: "memory");
}
template <int N> __device__ __forceinline__ void cp_wait() {
    asm volatile("cp.async.wait_group %0;" :: "n"(N) : "memory");
}
__device__ __forceinline__ void ldsm4(unsigned& r0, unsigned& r1, unsigned& r2,
                                      unsigned& r3, unsigned a) {
    asm volatile("ldmatrix.sync.aligned.m8n8.x4.shared.b16 {%0,%1,%2,%3}, [%4];"
                 : "=r"(r0), "=r"(r1), "=r"(r2), "=r"(r3) : "r"(a));
}
__device__ __forceinline__ void ldsm2(unsigned& r0, unsigned& r1, unsigned a) {
    asm volatile("ldmatrix.sync.aligned.m8n8.x2.shared.b16 {%0,%1}, [%2];"
                 : "=r"(r0), "=r"(r1) : "r"(a));
}
__device__ __forceinline__ void mma16816(float* d, const unsigned* a, const unsigned* b) {
    asm volatile("mma.sync.aligned.m16n8k16.row.col.f32.bf16.bf16.f32 "
                 "{%0,%1,%2,%3},{%4,%5,%6,%7},{%8,%9},{%0,%1,%2,%3};"
                 : "+f"(d[0]), "+f"(d[1]), "+f"(d[2]), "+f"(d[3])
                 : "r"(a[0]), "r"(a[1]), "r"(a[2]), "r"(a[3]), "r"(b[0]), "r"(b[1]));
}
__device__ __forceinline__ void wr_hl(__nv_bfloat16* h, __nv_bfloat16* l,
                                      size_t i, float v) {
    __nv_bfloat16 hh = __float2bfloat16(v);
    h[i] = hh;
    l[i] = __float2bfloat16(v - __bfloat162float(hh));
}
__device__ __forceinline__ unsigned pack_hl(float a, float b, unsigned& lo) {
    __nv_bfloat16 h0 = __float2bfloat16(a);
    __nv_bfloat16 h1 = __float2bfloat16(b);
    lo = (unsigned)__bfloat16_as_ushort(__float2bfloat16(a - __bfloat162float(h0))) |
         ((unsigned)__bfloat16_as_ushort(__float2bfloat16(b - __bfloat162float(h1))) << 16);
    return (unsigned)__bfloat16_as_ushort(h0) | ((unsigned)__bfloat16_as_ushort(h1) << 16);
}

// ---------------- HMMA split-bf16 GEMM: C = A @ W^T (+bias)(+relu) --------
// A,W bf16 hi/lo (K-major). 128 x NTILE tile per CTA, 8 warps (2x4).
// K multiple of 32. Optional fp32 C and/or bf16 hi/lo outputs, row gather.
template <int NTILE>
__global__ __launch_bounds__(256, 1) void gemm_mma(
    const __nv_bfloat16* __restrict__ Ah, const __nv_bfloat16* __restrict__ Al,
    const __nv_bfloat16* __restrict__ Wh, const __nv_bfloat16* __restrict__ Wl,
    const float* __restrict__ bias, float* __restrict__ C,
    __nv_bfloat16* __restrict__ Chi, __nv_bfloat16* __restrict__ Clo,
    int N, int K, int relu, const int* __restrict__ Arows)
{
    constexpr int LDS = 40;               // padded row stride (bf16): conflict-free ldmatrix
    constexpr int ASZ = 128 * LDS;        // elements per A sub-tile
    constexpr int WSZ = NTILE * LDS;
    constexpr int BUF = 2 * ASZ + 2 * WSZ;
    constexpr int WN  = NTILE / 4;        // warp col extent
    constexpr int NI  = WN / 8;           // n8 frags per warp
    extern __shared__ __nv_bfloat16 sm[];
    const unsigned sb = smem_u32(sm);
    const int tid = threadIdx.x;
    const int wid = tid >> 5, lane = tid & 31;
    const int rowTile = blockIdx.y * 128;
    const int colTile = blockIdx.x * NTILE;
    const int wm = (wid >> 2) * 64;       // warp row base
    const int wn = (wid & 3) * WN;        // warp col base

    const int nchunk = K >> 5;
    auto load_chunk = [&](int c) {
        const unsigned base = sb + (unsigned)(c & 1) * BUF * 2;
        const int k0 = c << 5;
        for (int i = tid; i < 512; i += 256) {
            int r = i >> 2, cc = (i & 3) << 3;
            int gr = rowTile + r; if (Arows) gr = Arows[gr];
            size_t go = (size_t)gr * K + k0 + cc;
            unsigned sa = base + (unsigned)(r * LDS + cc) * 2;
            cpa16(sa, Ah + go);
            cpa16(sa + ASZ * 2, Al + go);
        }
        for (int i = tid; i < NTILE * 4; i += 256) {
            int r = i >> 2, cc = (i & 3) << 3;
            size_t go = (size_t)(colTile + r) * K + k0 + cc;
            unsigned sa = base + (unsigned)(2 * ASZ + r * LDS + cc) * 2;
            cpa16(sa, Wh + go);
            cpa16(sa + WSZ * 2, Wl + go);
        }
    };

    float acc[4][NI][4];
#pragma unroll
    for (int mi = 0; mi < 4; mi++)
#pragma unroll
        for (int ni = 0; ni < NI; ni++)
#pragma unroll
            for (int j = 0; j < 4; j++) acc[mi][ni][j] = 0.0f;

    load_chunk(0); cp_commit();
    for (int c = 0; c < nchunk; c++) {
        if (c + 1 < nchunk) { load_chunk(c + 1); cp_commit(); cp_wait<1>(); }
        else cp_wait<0>();
        __syncthreads();
        const unsigned base = sb + (unsigned)(c & 1) * BUF * 2;
#pragma unroll
        for (int ks = 0; ks < 2; ks++) {
            const int kof = ks * 16 + ((lane >> 4) & 1) * 8;      // A col offset
            const int kof2 = ks * 16 + ((lane >> 3) & 1) * 8;     // B col offset
            unsigned ah[4][4], al[4][4], bh[NI][2], bl[NI][2];
#pragma unroll
            for (int mi = 0; mi < 4; mi++) {
                unsigned a = base + (unsigned)((wm + mi * 16 + (lane & 15)) * LDS + kof) * 2;
                ldsm4(ah[mi][0], ah[mi][1], ah[mi][2], ah[mi][3], a);
                ldsm4(al[mi][0], al[mi][1], al[mi][2], al[mi][3], a + ASZ * 2);
            }
#pragma unroll
            for (int ni = 0; ni < NI; ni++) {
                unsigned a = base + (unsigned)(2 * ASZ + (wn + ni * 8 + (lane & 7)) * LDS + kof2) * 2;
                ldsm2(bh[ni][0], bh[ni][1], a);
                ldsm2(bl[ni][0], bl[ni][1], a + WSZ * 2);
            }
#pragma unroll
            for (int mi = 0; mi < 4; mi++)
#pragma unroll
                for (int ni = 0; ni < NI; ni++) {
                    mma16816(acc[mi][ni], ah[mi], bh[ni]);
                    mma16816(acc[mi][ni], ah[mi], bl[ni]);
                    mma16816(acc[mi][ni], al[mi], bh[ni]);
                }
        }
        __syncthreads();
    }

    // epilogue: thread holds rows (wm+mi*16 + lane/4, +8), cols wn+ni*8+2*(lane&3)
    const int rbase = rowTile + wm + (lane >> 2);
    const int cbase = colTile + wn + 2 * (lane & 3);
#pragma unroll
    for (int mi = 0; mi < 4; mi++) {
#pragma unroll
        for (int ni = 0; ni < NI; ni++) {
            int cc = cbase + ni * 8;
            float b0 = bias ? bias[cc] : 0.0f;
            float b1 = bias ? bias[cc + 1] : 0.0f;
#pragma unroll
            for (int half = 0; half < 2; half++) {
                int r = rbase + mi * 16 + half * 8;
                float v0 = acc[mi][ni][half * 2 + 0] + b0;
                float v1 = acc[mi][ni][half * 2 + 1] + b1;
                if (relu) { v0 = fmaxf(v0, 0.0f); v1 = fmaxf(v1, 0.0f); }
                size_t o = (size_t)r * N + cc;
                if (C) *(float2*)(C + o) = make_float2(v0, v1);
                if (Chi) {
                    unsigned lo, hi = pack_hl(v0, v1, lo);
                    *(unsigned*)((unsigned short*)Chi + o) = hi;
                    *(unsigned*)((unsigned short*)Clo + o) = lo;
                }
            }
        }
    }
}

// ---------------- fp32 NT gemm (small cases) ----------------
__global__ void gemm_nt(const float* __restrict__ A, const float* __restrict__ W,
                        const float* __restrict__ bias, float* __restrict__ C,
                        int M, int N, int K)
{
    __shared__ float As[16][64];
    __shared__ float Ws[16][64];
    const int tid = threadIdx.x;
    const int rowTile = blockIdx.y * 64;
    const int colTile = blockIdx.x * 64;
    const int lr = tid >> 2;
    const int lc = (tid & 3) << 2;
    const int tr = (tid >> 4) << 2;
    const int tc = (tid & 15) << 2;
    const float* Aptr = A + (size_t)(rowTile + lr) * K + lc;
    const float* Wptr = W + (size_t)(colTile + lr) * K + lc;
    float acc[4][4] = {};
    for (int k0 = 0; k0 < K; k0 += 16) {
        float4 av = *reinterpret_cast<const float4*>(Aptr + k0);
        float4 wv = *reinterpret_cast<const float4*>(Wptr + k0);
        As[lc + 0][lr] = av.x; As[lc + 1][lr] = av.y; As[lc + 2][lr] = av.z; As[lc + 3][lr] = av.w;
        Ws[lc + 0][lr] = wv.x; Ws[lc + 1][lr] = wv.y; Ws[lc + 2][lr] = wv.z; Ws[lc + 3][lr] = wv.w;
        __syncthreads();
#pragma unroll
        for (int k = 0; k < 16; k++) {
            float4 a = *reinterpret_cast<const float4*>(&As[k][tr]);
            float4 b = *reinterpret_cast<const float4*>(&Ws[k][tc]);
            acc[0][0] += a.x * b.x; acc[0][1] += a.x * b.y; acc[0][2] += a.x * b.z; acc[0][3] += a.x * b.w;
            acc[1][0] += a.y * b.x; acc[1][1] += a.y * b.y; acc[1][2] += a.y * b.z; acc[1][3] += a.y * b.w;
            acc[2][0] += a.z * b.x; acc[2][1] += a.z * b.y; acc[2][2] += a.z * b.z; acc[2][3] += a.z * b.w;
            acc[3][0] += a.w * b.x; acc[3][1] += a.w * b.y; acc[3][2] += a.w * b.z; acc[3][3] += a.w * b.w;
        }
        __syncthreads();
    }
#pragma unroll
    for (int i = 0; i < 4; i++)
#pragma unroll
        for (int j = 0; j < 4; j++) {
            float v = acc[i][j] + (bias ? bias[colTile + tc + j] : 0.0f);
            C[(size_t)(rowTile + tr + i) * N + colTile + tc + j] = v;
        }
}

// ---------------- fused scan step ----------------
__global__ void gemm_scan(const float* __restrict__ cur, const float* __restrict__ dw,
                          const float* __restrict__ db, float* __restrict__ ct, int s)
{
    __shared__ float As[16][64];
    __shared__ float Ws[16][64];
    const int tid = threadIdx.x;
    const int rowTile = blockIdx.y * 64;
    const int colTile = blockIdx.x * 64;
    const int lr = tid >> 2;
    const int lc = (tid & 3) << 2;
    const int tr = (tid >> 4) << 2;
    const int tc = (tid & 15) << 2;
    int m = lr + rowTile;
    int b = m >> 6, p = m & 63;
    size_t g = (size_t)b * 2048 + s * 64 + p;
    const float* crow = cur + g * 256;
    const float* prow = ct + (g - 64) * 256;
    const float* Wptr = dw + (size_t)(colTile + lr) * 512 + lc;
    float acc[4][4] = {};
    for (int k0 = 0; k0 < 512; k0 += 16) {
        int kk = k0 + lc;
        float4 av;
        if (kk < 256) av = *reinterpret_cast<const float4*>(crow + kk);
        else {
            float4 a = *reinterpret_cast<const float4*>(crow + kk - 256);
            float4 q = *reinterpret_cast<const float4*>(prow + kk - 256);
            av = make_float4(a.x - q.x, a.y - q.y, a.z - q.z, a.w - q.w);
        }
        float4 wv = *reinterpret_cast<const float4*>(Wptr + k0);
        As[lc + 0][lr] = av.x; As[lc + 1][lr] = av.y; As[lc + 2][lr] = av.z; As[lc + 3][lr] = av.w;
        Ws[lc + 0][lr] = wv.x; Ws[lc + 1][lr] = wv.y; Ws[lc + 2][lr] = wv.z; Ws[lc + 3][lr] = wv.w;
        __syncthreads();
#pragma unroll
        for (int k = 0; k < 16; k++) {
            float4 a = *reinterpret_cast<const float4*>(&As[k][tr]);
            float4 bb = *reinterpret_cast<const float4*>(&Ws[k][tc]);
            acc[0][0] += a.x * bb.x; acc[0][1] += a.x * bb.y; acc[0][2] += a.x * bb.z; acc[0][3] += a.x * bb.w;
            acc[1][0] += a.y * bb.x; acc[1][1] += a.y * bb.y; acc[1][2] += a.y * bb.z; acc[1][3] += a.y * bb.w;
            acc[2][0] += a.z * bb.x; acc[2][1] += a.z * bb.y; acc[2][2] += a.z * bb.z; acc[2][3] += a.z * bb.w;
            acc[3][0] += a.w * bb.x; acc[3][1] += a.w * bb.y; acc[3][2] += a.w * bb.z; acc[3][3] += a.w * bb.w;
        }
        __syncthreads();
    }
#pragma unroll
    for (int i = 0; i < 4; i++) {
        int mm = rowTile + tr + i;
        int bb2 = mm >> 6, pp = mm & 63;
        size_t gg = (size_t)bb2 * 2048 + s * 64 + pp;
#pragma unroll
        for (int j = 0; j < 4; j++)
            ct[gg * 256 + colTile + tc + j] = acc[i][j] + db[colTile + tc + j];
    }
}

// ---------------- elementwise / attention / LN kernels --------------------
__global__ void conv_hl(const float* __restrict__ s, __nv_bfloat16* __restrict__ h,
                        __nv_bfloat16* __restrict__ l, int n)
{
    int i = blockIdx.x * blockDim.x + threadIdx.x;
    if (i < n) wr_hl(h, l, i, s[i]);
}

__global__ void expand_tok(const float* __restrict__ op, const float* __restrict__ pe,
                           float* __restrict__ x0, __nv_bfloat16* __restrict__ xh,
                           __nv_bfloat16* __restrict__ xl)
{
    size_t i = (size_t)blockIdx.x * blockDim.x + threadIdx.x;
    int d = (int)(i & 255);
    int row = (int)(i >> 8);
    int p = row & 63;
    int bs = row >> 6;
    float v = op[bs * 256 + d] + pe[p * 256 + d];
    x0[i] = v; wr_hl(xh, xl, i, v);
}

__global__ void sa_attn(const float* __restrict__ qkv, __nv_bfloat16* __restrict__ oh,
                        __nv_bfloat16* __restrict__ ol)
{
    __shared__ float qs[64][64];
    __shared__ float kt[64][64];
    __shared__ float ss[64][64];
    int n = blockIdx.x, h = blockIdx.y;
    int tid = threadIdx.x;
    const float* base = qkv + (size_t)n * 64 * 768 + h * 64;
#pragma unroll
    for (int i = 0; i < 16; i++) {
        int e = tid + i * 256, l = e >> 6, d = e & 63;
        qs[l][d] = base[l * 768 + d];
        kt[d][(l + d) & 63] = base[l * 768 + 256 + d];
    }
    __syncthreads();
#pragma unroll
    for (int i = 0; i < 16; i++) {
        int e = tid + i * 256, r = e >> 6, c = e & 63;
        float acc = 0.0f;
#pragma unroll
        for (int d = 0; d < 64; d++) acc += qs[r][d] * kt[d][(c + d) & 63];
        ss[r][(c + r) & 63] = acc * 0.125f;
    }
    __syncthreads();
#pragma unroll
    for (int i = 0; i < 16; i++) {
        int e = tid + i * 256, l = e >> 6, d = e & 63;
        kt[d][(l + d) & 63] = base[l * 768 + 512 + d];
    }
    if (tid < 64) {
        int r = tid;
        float mx = -1e30f;
        for (int j = 0; j < 64; j++) mx = fmaxf(mx, ss[r][(j + r) & 63]);
        float sum = 0.0f;
        for (int j = 0; j < 64; j++) {
            float e = expf(ss[r][(j + r) & 63] - mx);
            ss[r][(j + r) & 63] = e; sum += e;
        }
        float inv = 1.0f / sum;
        for (int j = 0; j < 64; j++) ss[r][(j + r) & 63] *= inv;
    }
    __syncthreads();
#pragma unroll
    for (int i = 0; i < 16; i++) {
        int e = tid + i * 256, r = e >> 6, c = e & 63;
        float acc = 0.0f;
#pragma unroll
        for (int j = 0; j < 64; j++) acc += ss[r][(j + r) & 63] * kt[c][(j + c) & 63];
        wr_hl(oh, ol, ((size_t)n * 64 + r) * 256 + h * 64 + c, acc);
    }
}

__global__ void ln_res(const float* __restrict__ x1, int ld1,
                       const float* __restrict__ x2,
                       const float* __restrict__ g, const float* __restrict__ b,
                       float* __restrict__ out, __nv_bfloat16* __restrict__ oh,
                       __nv_bfloat16* __restrict__ ol, int M)
{
    int gw = (int)((blockIdx.x * (size_t)blockDim.x + threadIdx.x) >> 5);
    int lane = threadIdx.x & 31;
    if (gw >= M) return;
    const float* r1 = x1 + (size_t)gw * ld1;
    const float* r2 = x2 ? x2 + (size_t)gw * 256 : nullptr;
    float v[8];
    float s = 0.0f;
#pragma unroll
    for (int i = 0; i < 8; i++) {
        float t = r1[lane + i * 32];
        if (r2) t += r2[lane + i * 32];
        v[i] = t; s += t;
    }
#pragma unroll
    for (int o = 16; o; o >>= 1) s += __shfl_xor_sync(0xffffffffu, s, o);
    float mean = s * (1.0f / 256.0f);
    float var = 0.0f;
#pragma unroll
    for (int i = 0; i < 8; i++) { float d = v[i] - mean; var += d * d; }
#pragma unroll
    for (int o = 16; o; o >>= 1) var += __shfl_xor_sync(0xffffffffu, var, o);
    float rstd = rsqrtf(var * (1.0f / 256.0f) + 1e-5f);
#pragma unroll
    for (int i = 0; i < 8; i++) {
        int d = lane + i * 32;
        float y = (v[i] - mean) * rstd * g[d] + b[d];
        size_t o2 = (size_t)gw * 256 + d;
        if (out) out[o2] = y;
        if (oh) wr_hl(oh, ol, o2, y);
    }
}

__global__ void window_gather(const float* __restrict__ tok, float* __restrict__ x,
                              __nv_bfloat16* __restrict__ xh, __nv_bfloat16* __restrict__ xl)
{
    size_t i = (size_t)blockIdx.x * blockDim.x + threadIdx.x;
    int d = (int)(i & 255);
    int row = (int)(i >> 8);
    int c = row & 3;
    int seq = row >> 2;
    int p = seq & 63;
    int bs = seq >> 2 >> 4;  // seq >> 6
    int s = (seq >> 6) & 31;
    int b = seq >> 11;
    int sp = s + c - 3;
    float v = (sp < 0) ? 0.0f : tok[(((size_t)(b * 32 + sp) * 64 + p) << 8) + d];
    x[i] = v; wr_hl(xh, xl, i, v);
}

__global__ void ctx_attn(const float* __restrict__ qkv, __nv_bfloat16* __restrict__ oh,
                         __nv_bfloat16* __restrict__ ol, int last_only)
{
    int gw = (int)((blockIdx.x * (size_t)blockDim.x + threadIdx.x) >> 5);
    int lane = threadIdx.x & 31;
    int seq = gw >> 2, h = gw & 3;
    if (seq >= 16384) return;
    const float* base = qkv + (size_t)seq * 4 * 768 + h * 64;
    float k[4][2], v[4][2];
#pragma unroll
    for (int c = 0; c < 4; c++) {
        k[c][0] = base[c * 768 + 256 + lane];  k[c][1] = base[c * 768 + 256 + lane + 32];
        v[c][0] = base[c * 768 + 512 + lane];  v[c][1] = base[c * 768 + 512 + lane + 32];
    }
    if (last_only) {
        float q0 = base[3 * 768 + lane], q1 = base[3 * 768 + lane + 32];
        float p[4];
#pragma unroll
        for (int j = 0; j < 4; j++) {
            float s = q0 * k[j][0] + q1 * k[j][1];
#pragma unroll
            for (int o = 16; o; o >>= 1) s += __shfl_xor_sync(0xffffffffu, s, o);
            p[j] = s * 0.125f;
        }
        float mx = fmaxf(fmaxf(p[0], p[1]), fmaxf(p[2], p[3]));
        float e0 = expf(p[0] - mx), e1 = expf(p[1] - mx), e2 = expf(p[2] - mx), e3 = expf(p[3] - mx);
        float inv = 1.0f / (e0 + e1 + e2 + e3);
        p[0] = e0 * inv; p[1] = e1 * inv; p[2] = e2 * inv; p[3] = e3 * inv;
        float o0 = p[0] * v[0][0] + p[1] * v[1][0] + p[2] * v[2][0] + p[3] * v[3][0];
        float o1 = p[0] * v[0][1] + p[1] * v[1][1] + p[2] * v[2][1] + p[3] * v[3][1];
        wr_hl(oh, ol, (size_t)seq * 256 + h * 64 + lane, o0);
        wr_hl(oh, ol, (size_t)seq * 256 + h * 64 + lane + 32, o1);
    } else {
        float q[4][2];
#pragma unroll
        for (int c = 0; c < 4; c++) {
            q[c][0] = base[c * 768 + lane]; q[c][1] = base[c * 768 + lane + 32];
        }
        float p[4][4];
#pragma unroll
        for (int i = 0; i < 4; i++) {
#pragma unroll
            for (int j = 0; j < 4; j++) {
                float s = q[i][0] * k[j][0] + q[i][1] * k[j][1];
#pragma unroll
                for (int o = 16; o; o >>= 1) s += __shfl_xor_sync(0xffffffffu, s, o);
                p[i][j] = s * 0.125f;
            }
            float mx = fmaxf(fmaxf(p[i][0], p[i][1]), fmaxf(p[i][2], p[i][3]));
            float e0 = expf(p[i][0] - mx), e1 = expf(p[i][1] - mx);
            float e2 = expf(p[i][2] - mx), e3 = expf(p[i][3] - mx);
            float inv = 1.0f / (e0 + e1 + e2 + e3);
            p[i][0] = e0 * inv; p[i][1] = e1 * inv; p[i][2] = e2 * inv; p[i][3] = e3 * inv;
        }
#pragma unroll
        for (int i = 0; i < 4; i++) {
            float o0 = p[i][0] * v[0][0] + p[i][1] * v[1][0] + p[i][2] * v[2][0] + p[i][3] * v[3][0];
            float o1 = p[i][0] * v[0][1] + p[i][1] * v[1][1] + p[i][2] * v[2][1] + p[i][3] * v[3][1];
            size_t row = (size_t)seq * 4 + i;
            wr_hl(oh, ol, row * 256 + h * 64 + lane, o0);
            wr_hl(oh, ol, row * 256 + h * 64 + lane + 32, o1);
        }
    }
}

__global__ void copy_out0(const float* __restrict__ cur, float* __restrict__ ct)
{
    int i = blockIdx.x * blockDim.x + threadIdx.x;
    int d = i & 255; int m = i >> 8;
    int b = m >> 6, p = m & 63;
    size_t r = ((size_t)b * 2048 + p) * 256 + d;
    ct[r] = cur[r];
}

__global__ void cb_norms(const float* __restrict__ cb, float* __restrict__ cn)
{
    int gw = (int)((blockIdx.x * (size_t)blockDim.x + threadIdx.x) >> 5);
    int lane = threadIdx.x & 31;
    if (gw >= 1024) return;
    const float* r = cb + (size_t)gw * 256;
    float s = 0.0f;
#pragma unroll
    for (int i = 0; i < 8; i++) { float v = r[lane + i * 32]; s += v * v; }
#pragma unroll
    for (int o = 16; o; o >>= 1) s += __shfl_xor_sync(0xffffffffu, s, o);
    if (!lane) cn[gw] = s;
}

__global__ void vq_argmin(const float* __restrict__ x, const float* __restrict__ scores,
                          const float* __restrict__ cn, int* __restrict__ idx)
{
    int gw = (int)((blockIdx.x * (size_t)blockDim.x + threadIdx.x) >> 5);
    int lane = threadIdx.x & 31;
    if (gw >= 16384) return;
    const float* xr = x + (size_t)gw * 256;
    float xx = 0.0f;
#pragma unroll
    for (int i = 0; i < 8; i++) { float v = xr[lane + i * 32]; xx += v * v; }
#pragma unroll
    for (int o = 16; o; o >>= 1) xx += __shfl_xor_sync(0xffffffffu, xx, o);
    const float* sr = scores + (size_t)gw * 1024;
    float best = 3.4e38f; int bi = 0x7fffffff;
    for (int j = lane; j < 1024; j += 32) {
        float d = (xx - 2.0f * sr[j]) + cn[j];
        if (d < best || (d == best && j < bi)) { best = d; bi = j; }
    }
#pragma unroll
    for (int o = 16; o; o >>= 1) {
        float ob = __shfl_xor_sync(0xffffffffu, best, o);
        int   oi = __shfl_xor_sync(0xffffffffu, bi, o);
        if (ob < best || (ob == best && oi < bi)) { best = ob; bi = oi; }
    }
    if (!lane) idx[gw] = bi;
}

__global__ void mse_partial(const float* __restrict__ x, const float* __restrict__ cb,
                            const int* __restrict__ idx, float* __restrict__ red)
{
    __shared__ float sm[256];
    float s = 0.0f;
    size_t stride = (size_t)gridDim.x * blockDim.x;
    for (size_t i = (size_t)blockIdx.x * blockDim.x + threadIdx.x;
         i < (size_t)16384 * 256; i += stride) {
        int row = (int)(i >> 8), d = (int)(i & 255);
        float diff = x[i] - cb[(size_t)idx[row] * 256 + d];
        s += diff * diff;
    }
    sm[threadIdx.x] = s; __syncthreads();
    for (int o = 128; o; o >>= 1) {
        if ((int)threadIdx.x < o) sm[threadIdx.x] += sm[threadIdx.x + o];
        __syncthreads();
    }
    if (!threadIdx.x) red[blockIdx.x] = sm[0];
}

__global__ void mse_final(const float* __restrict__ red, float* __restrict__ out)
{
    __shared__ float sm[256];
    sm[threadIdx.x] = red[threadIdx.x]; __syncthreads();
    for (int o = 128; o; o >>= 1) {
        if ((int)threadIdx.x < o) sm[threadIdx.x] += sm[threadIdx.x + o];
        __syncthreads();
    }
    if (!threadIdx.x) {
        float mse = sm[0] / 4194304.0f;
        out[1064960] = 0.25f * mse;
        out[1064961] = mse;
        out[1064962] = 1.25f * mse;
    }
}

__global__ void idx_write(const int* __restrict__ idx, float* __restrict__ out)
{
    int i = blockIdx.x * blockDim.x + threadIdx.x;
    if (i < 16384) out[1048576 + i] = (float)idx[i];
}

// ---------------- host ----------------
static inline void* symp(const void* s)
{
    void* p = nullptr;
    cudaGetSymbolAddress(&p, s);
    return p;
}

extern "C" void kernel_launch(void* const* d_in, const int* in_sizes, int n_in,
                              void* d_out, int out_size)
{
    (void)in_sizes; (void)n_in; (void)out_size;
    const float* obs      = (const float*)d_in[0];
    const float* patch_w  = (const float*)d_in[2];
    const float* patch_b  = (const float*)d_in[3];
    const float* pos_emb  = (const float*)d_in[4];
    const float* sa_qkv_w = (const float*)d_in[5];
    const float* sa_qkv_b = (const float*)d_in[6];
    const float* sa_out_w = (const float*)d_in[7];
    const float* sa_out_b = (const float*)d_in[8];
    const float* sa_ln_g  = (const float*)d_in[9];
    const float* sa_ln_b  = (const float*)d_in[10];
    const float* cqkv_w   = (const float*)d_in[11];
    const float* cqkv_b   = (const float*)d_in[12];
    const float* cout_w   = (const float*)d_in[13];
    const float* cout_b   = (const float*)d_in[14];
    const float* cff1_w   = (const float*)d_in[15];
    const float* cff1_b   = (const float*)d_in[16];
    const float* cff2_w   = (const float*)d_in[17];
    const float* cff2_b   = (const float*)d_in[18];
    const float* cln1_g   = (const float*)d_in[19];
    const float* cln1_b   = (const float*)d_in[20];
    const float* cln2_g   = (const float*)d_in[21];
    const float* cln2_b   = (const float*)d_in[22];
    const float* delta_w  = (const float*)d_in[23];
    const float* delta_b  = (const float*)d_in[24];
    const float* codebook = (const float*)d_in[25];
    const float* dec_w1   = (const float*)d_in[26];
    const float* dec_b1   = (const float*)d_in[27];
    const float* dec_w2   = (const float*)d_in[28];
    const float* dec_b2   = (const float*)d_in[29];
    const float* dec_w3   = (const float*)d_in[30];
    const float* dec_b3   = (const float*)d_in[31];
    float* out = (float*)d_out;

    float* obsproj = (float*)symp(g_obsproj);
    float* x0      = (float*)symp(g_x0);
    float* qkv     = (float*)symp(g_qkv);
    float* proj    = (float*)symp(g_proj);
    float* tok     = (float*)symp(g_tok);
    float* xctx    = (float*)symp(g_xctx);
    float* hid     = (float*)symp(g_hid);
    float* xlast   = (float*)symp(g_xlast);
    float* cur     = (float*)symp(g_cur);
    float* ctxtok  = (float*)symp(g_ctxtok);
    float* cn      = (float*)symp(g_cn);
    float* red     = (float*)symp(g_red);
    int*   vidx    = (int*)symp(g_idx);
    __nv_bfloat16* x0h = (__nv_bfloat16*)symp(g_x0h);
    __nv_bfloat16* x0l = (__nv_bfloat16*)symp(g_x0l);
    __nv_bfloat16* ath = (__nv_bfloat16*)symp(g_ath);
    __nv_bfloat16* atl = (__nv_bfloat16*)symp(g_atl);
    __nv_bfloat16* xh  = (__nv_bfloat16*)symp(g_xh);
    __nv_bfloat16* xl  = (__nv_bfloat16*)symp(g_xl);
    __nv_bfloat16* hh  = (__nv_bfloat16*)symp(g_hh);
    __nv_bfloat16* hl  = (__nv_bfloat16*)symp(g_hl);
    __nv_bfloat16* xlh = (__nv_bfloat16*)symp(g_xlh);
    __nv_bfloat16* xll = (__nv_bfloat16*)symp(g_xll);
    __nv_bfloat16* cth = (__nv_bfloat16*)symp(g_cth);
    __nv_bfloat16* ctl = (__nv_bfloat16*)symp(g_ctl);
    __nv_bfloat16* wh  = (__nv_bfloat16*)symp(g_wh);
    __nv_bfloat16* wl  = (__nv_bfloat16*)symp(g_wl);

    // dynamic smem: 2 buffers * (2*128 + 2*NTILE) rows * 40 bf16 * 2B
    const int SM128 = 2 * (2 * 128 * 40 + 2 * 128 * 40) * 2;  // 81920
    const int SM64  = 2 * (2 * 128 * 40 + 2 * 64 * 40) * 2;   // 61440
    cudaFuncSetAttribute(gemm_mma<128>, cudaFuncAttributeMaxDynamicSharedMemorySize, SM128);
    cudaFuncSetAttribute(gemm_mma<64>,  cudaFuncAttributeMaxDynamicSharedMemorySize, SM64);

    const int T = 256;
    auto cv = [&](const float* src, int off, int n) {
        conv_hl<<<(n + 255) / 256, 256>>>(src, wh + off, wl + off, n);
    };
    cv(sa_qkv_w, OFF_SAQKV, 196608);
    cv(sa_out_w, OFF_SAOUT, 65536);
    cv(cqkv_w,            OFF_CQKV0, 196608);
    cv(cqkv_w + 196608,   OFF_CQKV1, 196608);
    cv(cout_w,            OFF_COUT0, 65536);
    cv(cout_w + 65536,    OFF_COUT1, 65536);
    cv(cff1_w,            OFF_FF1_0, 262144);
    cv(cff1_w + 262144,   OFF_FF1_1, 262144);
    cv(cff2_w,            OFF_FF2_0, 262144);
    cv(cff2_w + 262144,   OFF_FF2_1, 262144);
    cv(codebook,          OFF_CB,    262144);
    cv(dec_w1,            OFF_D1,    262144);
    cv(dec_w2,            OFF_D2,    1048576);
    cv(dec_w3,            OFF_D3,    65536);

    auto tc = [&](const __nv_bfloat16* Ah, const __nv_bfloat16* Al, int woff,
                  const float* bias, float* C, __nv_bfloat16* Chi, __nv_bfloat16* Clo,
                  int M, int N, int K, int relu, const int* Arows) {
        gemm_mma<128><<<dim3(N / 128, M / 128), 256, SM128>>>(
            Ah, Al, wh + woff, wl + woff, bias, C, Chi, Clo, N, K, relu, Arows);
    };

    // 1) patch projection + positional embed
    gemm_nt<<<dim3(4, 4), T>>>(obs, patch_w, patch_b, obsproj, 256, 256, 64);
    expand_tok<<<16384, T>>>(obsproj, pos_emb, x0, x0h, x0l);

    // 2) self-attention block
    tc(x0h, x0l, OFF_SAQKV, sa_qkv_b, qkv, nullptr, nullptr, 16384, 768, 256, 0, nullptr);
    sa_attn<<<dim3(256, 4), T>>>(qkv, ath, atl);
    tc(ath, atl, OFF_SAOUT, sa_out_b, proj, nullptr, nullptr, 16384, 256, 256, 0, nullptr);
    ln_res<<<2048, T>>>(proj, 256, x0, sa_ln_g, sa_ln_b, tok, nullptr, nullptr, 16384);

    // 3) windowed context gather
    window_gather<<<65536, T>>>(tok, xctx, xh, xl);

    // 4) context layer 0
    tc(xh, xl, OFF_CQKV0, cqkv_b, qkv, nullptr, nullptr, 65536, 768, 256, 0, nullptr);
    ctx_attn<<<8192, T>>>(qkv, ath, atl, 0);
    tc(ath, atl, OFF_COUT0, cout_b, proj, nullptr, nullptr, 65536, 256, 256, 0, nullptr);
    ln_res<<<8192, T>>>(xctx, 256, proj, cln1_g, cln1_b, xctx, xh, xl, 65536);
    tc(xh, xl, OFF_FF1_0, cff1_b, nullptr, hh, hl, 65536, 1024, 256, 1, nullptr);
    tc(hh, hl, OFF_FF2_0, cff2_b, proj, nullptr, nullptr, 65536, 256, 1024, 0, nullptr);
    ln_res<<<8192, T>>>(xctx, 256, proj, cln2_g, cln2_b, xctx, xh, xl, 65536);

    // 5) context layer 1 — only last position consumed downstream
    tc(xh, xl, OFF_CQKV1, cqkv_b + 768, qkv, nullptr, nullptr, 65536, 768, 256, 0, nullptr);
    ctx_attn<<<8192, T>>>(qkv, ath, atl, 1);
    tc(ath, atl, OFF_COUT1, cout_b + 256, proj, nullptr, nullptr, 16384, 256, 256, 0, nullptr);
    ln_res<<<2048, T>>>(xctx + 768, 1024, proj, cln1_g + 256, cln1_b + 256, xlast, xlh, xll, 16384);
    tc(xlh, xll, OFF_FF1_1, cff1_b + 1024, nullptr, hh, hl, 16384, 1024, 256, 1, nullptr);
    tc(hh, hl, OFF_FF2_1, cff2_b + 256, proj, nullptr, nullptr, 16384, 256, 1024, 0, nullptr);
    ln_res<<<2048, T>>>(xlast, 256, proj, cln2_g + 256, cln2_b + 256, cur, nullptr, nullptr, 16384);

    // 6) sequential delta scan
    copy_out0<<<512, T>>>(cur, ctxtok);
    for (int s = 1; s < 32; s++)
        gemm_scan<<<dim3(4, 8), T>>>(cur, delta_w, delta_b, ctxtok, s);
    conv_hl<<<16384, 256>>>(ctxtok, cth, ctl, 16384 * 256);

    // 7) VQ
    cb_norms<<<128, T>>>(codebook, cn);
    tc(cth, ctl, OFF_CB, nullptr, hid, nullptr, nullptr, 16384, 1024, 256, 0, nullptr);
    vq_argmin<<<2048, T>>>(ctxtok, hid, cn, vidx);

    // 8) losses + idx
    mse_partial<<<256, T>>>(ctxtok, codebook, vidx, red);
    mse_final<<<1, T>>>(red, out);
    idx_write<<<64, T>>>(vidx, out);

    // 9) decoder (A = codebook[idx] gathered in loader)
    tc(wh + OFF_CB, wl + OFF_CB, OFF_D1, dec_b1, nullptr, ath, atl, 16384, 1024, 256, 1, vidx);
    tc(ath, atl, OFF_D2, dec_b2, nullptr, xh, xl, 16384, 1024, 1024, 1, nullptr);
    gemm_mma<64><<<dim3(1, 128), 256, SM64>>>(
        xh, xl, wh + OFF_D3, wl + OFF_D3, dec_b3, out, nullptr, nullptr, 64, 1024, 0, nullptr);
}

// round 7
// speedup vs baseline: 2.1315x; 1.0010x over previous
#include <cuda_runtime.h>
#include <cuda_bf16.h>
#include <math.h>

// B=8 S=32 P=64 D=256 H=1024 K=1024 OBS=64 CTX=4 NH=4 dh=64
// rows: BS=256, BSP=16384, BSP*CTX=65536

// ---------------- scratch ----------------
__device__ float g_obsproj[256 * 256];
__device__ float g_x0[16384 * 256];
__device__ float g_qkv[65536 * 768];
__device__ float g_proj[65536 * 256];
__device__ float g_tok[16384 * 256];
__device__ float g_xctx[65536 * 256];
__device__ float g_hid[16384 * 1024];        // VQ scores
__device__ float g_xlast[16384 * 256];
__device__ float g_cur[16384 * 256];
__device__ float g_ctxtok[16384 * 256];
__device__ float g_cn[1024];
__device__ float g_red[256];
__device__ int   g_idx[16384];

// bf16 hi/lo activation buffers
__device__ __nv_bfloat16 g_x0h[16384 * 256],  g_x0l[16384 * 256];
__device__ __nv_bfloat16 g_ath[65536 * 256],  g_atl[65536 * 256];
__device__ __nv_bfloat16 g_xh [65536 * 256],  g_xl [65536 * 256];
__device__ __nv_bfloat16 g_hh [65536 * 1024], g_hl [65536 * 1024];
__device__ __nv_bfloat16 g_xlh[16384 * 256],  g_xll[16384 * 256];
__device__ __nv_bfloat16 g_cth[16384 * 256],  g_ctl[16384 * 256];
__device__ __nv_bfloat16 g_wh [3538944],      g_wl [3538944];

// weight pool offsets (elements)
#define OFF_SAQKV 0
#define OFF_SAOUT 196608
#define OFF_CQKV0 262144
#define OFF_CQKV1 458752
#define OFF_COUT0 655360
#define OFF_COUT1 720896
#define OFF_FF1_0 786432
#define OFF_FF1_1 1048576
#define OFF_FF2_0 1310720
#define OFF_FF2_1 1572864
#define OFF_CB    1835008
#define OFF_D1    2097152
#define OFF_D2    2359296
#define OFF_D3    3407872

// ---------------- PTX helpers ----------------
__device__ __forceinline__ unsigned smem_u32(const void* p) {
    unsigned a;
    asm("{ .reg .u64 t; cvta.to.shared.u64 t, %1; cvt.u32.u64 %0, t; }"
        : "=r"(a) : "l"(p));
    return a;
}
__device__ __forceinline__ void cpa16(unsigned s, const void* g) {
    asm volatile("cp.async.cg.shared.global [%0], [%1], 16;"
                 :: "r"(s), "l"(g) : "memory");
}
__device__ __forceinline__ void cp_commit() {
    asm volatile("cp.async.commit_group;" ::: "memory");
}
template <int N> __device__ __forceinline__ void cp_wait() {
    asm volatile("cp.async.wait_group %0;" :: "n"(N) : "memory");
}
__device__ __forceinline__ void ldsm4(unsigned& r0, unsigned& r1, unsigned& r2,
                                      unsigned& r3, unsigned a) {
    asm volatile("ldmatrix.sync.aligned.m8n8.x4.shared.b16 {%0,%1,%2,%3}, [%4];"
                 : "=r"(r0), "=r"(r1), "=r"(r2), "=r"(r3) : "r"(a));
}
__device__ __forceinline__ void ldsm2(unsigned& r0, unsigned& r1, unsigned a) {
    asm volatile("ldmatrix.sync.aligned.m8n8.x2.shared.b16 {%0,%1}, [%2];"
                 : "=r"(r0), "=r"(r1) : "r"(a));
}
__device__ __forceinline__ void mma16816(float* d, const unsigned* a, const unsigned* b) {
    asm volatile("mma.sync.aligned.m16n8k16.row.col.f32.bf16.bf16.f32 "
                 "{%0,%1,%2,%3},{%4,%5,%6,%7},{%8,%9},{%0,%1,%2,%3};"
                 : "+f"(d[0]), "+f"(d[1]), "+f"(d[2]), "+f"(d[3])
                 : "r"(a[0]), "r"(a[1]), "r"(a[2]), "r"(a[3]), "r"(b[0]), "r"(b[1]));
}
__device__ __forceinline__ void wr_hl(__nv_bfloat16* h, __nv_bfloat16* l,
                                      size_t i, float v) {
    __nv_bfloat16 hh = __float2bfloat16(v);
    h[i] = hh;
    l[i] = __float2bfloat16(v - __bfloat162float(hh));
}
__device__ __forceinline__ unsigned pack_hl(float a, float b, unsigned& lo) {
    __nv_bfloat16 h0 = __float2bfloat16(a);
    __nv_bfloat16 h1 = __float2bfloat16(b);
    lo = (unsigned)__bfloat16_as_ushort(__float2bfloat16(a - __bfloat162float(h0))) |
         ((unsigned)__bfloat16_as_ushort(__float2bfloat16(b - __bfloat162float(h1))) << 16);
    return (unsigned)__bfloat16_as_ushort(h0) | ((unsigned)__bfloat16_as_ushort(h1) << 16);
}

// ---------------- HMMA split-bf16 GEMM: C = A @ W^T (+bias)(+relu) --------
// A,W bf16 hi/lo (K-major). 128 x NTILE tile per CTA, 8 warps (2x4).
// K multiple of 32. Optional fp32 C and/or bf16 hi/lo outputs, row gather.
template <int NTILE>
__global__ __launch_bounds__(256, 1) void gemm_mma(
    const __nv_bfloat16* __restrict__ Ah, const __nv_bfloat16* __restrict__ Al,
    const __nv_bfloat16* __restrict__ Wh, const __nv_bfloat16* __restrict__ Wl,
    const float* __restrict__ bias, float* __restrict__ C,
    __nv_bfloat16* __restrict__ Chi, __nv_bfloat16* __restrict__ Clo,
    int N, int K, int relu, const int* __restrict__ Arows)
{
    constexpr int LDS = 40;               // padded row stride (bf16): conflict-free ldmatrix
    constexpr int ASZ = 128 * LDS;        // elements per A sub-tile
    constexpr int WSZ = NTILE * LDS;
    constexpr int BUF = 2 * ASZ + 2 * WSZ;
    constexpr int WN  = NTILE / 4;        // warp col extent
    constexpr int NI  = WN / 8;           // n8 frags per warp
    extern __shared__ __nv_bfloat16 sm[];
    const unsigned sb = smem_u32(sm);
    const int tid = threadIdx.x;
    const int wid = tid >> 5, lane = tid & 31;
    const int rowTile = blockIdx.y * 128;
    const int colTile = blockIdx.x * NTILE;
    const int wm = (wid >> 2) * 64;       // warp row base
    const int wn = (wid & 3) * WN;        // warp col base

    const int nchunk = K >> 5;
    auto load_chunk = [&](int c) {
        const unsigned base = sb + (unsigned)(c & 1) * BUF * 2;
        const int k0 = c << 5;
        for (int i = tid; i < 512; i += 256) {
            int r = i >> 2, cc = (i & 3) << 3;
            int gr = rowTile + r; if (Arows) gr = Arows[gr];
            size_t go = (size_t)gr * K + k0 + cc;
            unsigned sa = base + (unsigned)(r * LDS + cc) * 2;
            cpa16(sa, Ah + go);
            cpa16(sa + ASZ * 2, Al + go);
        }
        for (int i = tid; i < NTILE * 4; i += 256) {
            int r = i >> 2, cc = (i & 3) << 3;
            size_t go = (size_t)(colTile + r) * K + k0 + cc;
            unsigned sa = base + (unsigned)(2 * ASZ + r * LDS + cc) * 2;
            cpa16(sa, Wh + go);
            cpa16(sa + WSZ * 2, Wl + go);
        }
    };

    float acc[4][NI][4];
#pragma unroll
    for (int mi = 0; mi < 4; mi++)
#pragma unroll
        for (int ni = 0; ni < NI; ni++)
#pragma unroll
            for (int j = 0; j < 4; j++) acc[mi][ni][j] = 0.0f;

    load_chunk(0); cp_commit();
    for (int c = 0; c < nchunk; c++) {
        if (c + 1 < nchunk) { load_chunk(c + 1); cp_commit(); cp_wait<1>(); }
        else cp_wait<0>();
        __syncthreads();
        const unsigned base = sb + (unsigned)(c & 1) * BUF * 2;
#pragma unroll
        for (int ks = 0; ks < 2; ks++) {
            const int kof = ks * 16 + ((lane >> 4) & 1) * 8;      // A col offset
            const int kof2 = ks * 16 + ((lane >> 3) & 1) * 8;     // B col offset
            unsigned ah[4][4], al[4][4], bh[NI][2], bl[NI][2];
#pragma unroll
            for (int mi = 0; mi < 4; mi++) {
                unsigned a = base + (unsigned)((wm + mi * 16 + (lane & 15)) * LDS + kof) * 2;
                ldsm4(ah[mi][0], ah[mi][1], ah[mi][2], ah[mi][3], a);
                ldsm4(al[mi][0], al[mi][1], al[mi][2], al[mi][3], a + ASZ * 2);
            }
#pragma unroll
            for (int ni = 0; ni < NI; ni++) {
                unsigned a = base + (unsigned)(2 * ASZ + (wn + ni * 8 + (lane & 7)) * LDS + kof2) * 2;
                ldsm2(bh[ni][0], bh[ni][1], a);
                ldsm2(bl[ni][0], bl[ni][1], a + WSZ * 2);
            }
#pragma unroll
            for (int mi = 0; mi < 4; mi++)
#pragma unroll
                for (int ni = 0; ni < NI; ni++) {
                    mma16816(acc[mi][ni], ah[mi], bh[ni]);
                    mma16816(acc[mi][ni], ah[mi], bl[ni]);
                    mma16816(acc[mi][ni], al[mi], bh[ni]);
                }
        }
        __syncthreads();
    }

    // epilogue: thread holds rows (wm+mi*16 + lane/4, +8), cols wn+ni*8+2*(lane&3)
    const int rbase = rowTile + wm + (lane >> 2);
    const int cbase = colTile + wn + 2 * (lane & 3);
#pragma unroll
    for (int mi = 0; mi < 4; mi++) {
#pragma unroll
        for (int ni = 0; ni < NI; ni++) {
            int cc = cbase + ni * 8;
            float b0 = bias ? bias[cc] : 0.0f;
            float b1 = bias ? bias[cc + 1] : 0.0f;
#pragma unroll
            for (int half = 0; half < 2; half++) {
                int r = rbase + mi * 16 + half * 8;
                float v0 = acc[mi][ni][half * 2 + 0] + b0;
                float v1 = acc[mi][ni][half * 2 + 1] + b1;
                if (relu) { v0 = fmaxf(v0, 0.0f); v1 = fmaxf(v1, 0.0f); }
                size_t o = (size_t)r * N + cc;
                if (C) *(float2*)(C + o) = make_float2(v0, v1);
                if (Chi) {
                    unsigned lo, hi = pack_hl(v0, v1, lo);
                    *(unsigned*)((unsigned short*)Chi + o) = hi;
                    *(unsigned*)((unsigned short*)Clo + o) = lo;
                }
            }
        }
    }
}

// ---------------- fp32 NT gemm (small cases) ----------------
__global__ void gemm_nt(const float* __restrict__ A, const float* __restrict__ W,
                        const float* __restrict__ bias, float* __restrict__ C,
                        int M, int N, int K)
{
    __shared__ float As[16][64];
    __shared__ float Ws[16][64];
    const int tid = threadIdx.x;
    const int rowTile = blockIdx.y * 64;
    const int colTile = blockIdx.x * 64;
    const int lr = tid >> 2;
    const int lc = (tid & 3) << 2;
    const int tr = (tid >> 4) << 2;
    const int tc = (tid & 15) << 2;
    const float* Aptr = A + (size_t)(rowTile + lr) * K + lc;
    const float* Wptr = W + (size_t)(colTile + lr) * K + lc;
    float acc[4][4] = {};
    for (int k0 = 0; k0 < K; k0 += 16) {
        float4 av = *reinterpret_cast<const float4*>(Aptr + k0);
        float4 wv = *reinterpret_cast<const float4*>(Wptr + k0);
        As[lc + 0][lr] = av.x; As[lc + 1][lr] = av.y; As[lc + 2][lr] = av.z; As[lc + 3][lr] = av.w;
        Ws[lc + 0][lr] = wv.x; Ws[lc + 1][lr] = wv.y; Ws[lc + 2][lr] = wv.z; Ws[lc + 3][lr] = wv.w;
        __syncthreads();
#pragma unroll
        for (int k = 0; k < 16; k++) {
            float4 a = *reinterpret_cast<const float4*>(&As[k][tr]);
            float4 b = *reinterpret_cast<const float4*>(&Ws[k][tc]);
            acc[0][0] += a.x * b.x; acc[0][1] += a.x * b.y; acc[0][2] += a.x * b.z; acc[0][3] += a.x * b.w;
            acc[1][0] += a.y * b.x; acc[1][1] += a.y * b.y; acc[1][2] += a.y * b.z; acc[1][3] += a.y * b.w;
            acc[2][0] += a.z * b.x; acc[2][1] += a.z * b.y; acc[2][2] += a.z * b.z; acc[2][3] += a.z * b.w;
            acc[3][0] += a.w * b.x; acc[3][1] += a.w * b.y; acc[3][2] += a.w * b.z; acc[3][3] += a.w * b.w;
        }
        __syncthreads();
    }
#pragma unroll
    for (int i = 0; i < 4; i++)
#pragma unroll
        for (int j = 0; j < 4; j++) {
            float v = acc[i][j] + (bias ? bias[colTile + tc + j] : 0.0f);
            C[(size_t)(rowTile + tr + i) * N + colTile + tc + j] = v;
        }
}

// ---------------- fused scan step ----------------
__global__ void gemm_scan(const float* __restrict__ cur, const float* __restrict__ dw,
                          const float* __restrict__ db, float* __restrict__ ct, int s)
{
    __shared__ float As[16][64];
    __shared__ float Ws[16][64];
    const int tid = threadIdx.x;
    const int rowTile = blockIdx.y * 64;
    const int colTile = blockIdx.x * 64;
    const int lr = tid >> 2;
    const int lc = (tid & 3) << 2;
    const int tr = (tid >> 4) << 2;
    const int tc = (tid & 15) << 2;
    int m = lr + rowTile;
    int b = m >> 6, p = m & 63;
    size_t g = (size_t)b * 2048 + s * 64 + p;
    const float* crow = cur + g * 256;
    const float* prow = ct + (g - 64) * 256;
    const float* Wptr = dw + (size_t)(colTile + lr) * 512 + lc;
    float acc[4][4] = {};
    for (int k0 = 0; k0 < 512; k0 += 16) {
        int kk = k0 + lc;
        float4 av;
        if (kk < 256) av = *reinterpret_cast<const float4*>(crow + kk);
        else {
            float4 a = *reinterpret_cast<const float4*>(crow + kk - 256);
            float4 q = *reinterpret_cast<const float4*>(prow + kk - 256);
            av = make_float4(a.x - q.x, a.y - q.y, a.z - q.z, a.w - q.w);
        }
        float4 wv = *reinterpret_cast<const float4*>(Wptr + k0);
        As[lc + 0][lr] = av.x; As[lc + 1][lr] = av.y; As[lc + 2][lr] = av.z; As[lc + 3][lr] = av.w;
        Ws[lc + 0][lr] = wv.x; Ws[lc + 1][lr] = wv.y; Ws[lc + 2][lr] = wv.z; Ws[lc + 3][lr] = wv.w;
        __syncthreads();
#pragma unroll
        for (int k = 0; k < 16; k++) {
            float4 a = *reinterpret_cast<const float4*>(&As[k][tr]);
            float4 bb = *reinterpret_cast<const float4*>(&Ws[k][tc]);
            acc[0][0] += a.x * bb.x; acc[0][1] += a.x * bb.y; acc[0][2] += a.x * bb.z; acc[0][3] += a.x * bb.w;
            acc[1][0] += a.y * bb.x; acc[1][1] += a.y * bb.y; acc[1][2] += a.y * bb.z; acc[1][3] += a.y * bb.w;
            acc[2][0] += a.z * bb.x; acc[2][1] += a.z * bb.y; acc[2][2] += a.z * bb.z; acc[2][3] += a.z * bb.w;
            acc[3][0] += a.w * bb.x; acc[3][1] += a.w * bb.y; acc[3][2] += a.w * bb.z; acc[3][3] += a.w * bb.w;
        }
        __syncthreads();
    }
#pragma unroll
    for (int i = 0; i < 4; i++) {
        int mm = rowTile + tr + i;
        int bb2 = mm >> 6, pp = mm & 63;
        size_t gg = (size_t)bb2 * 2048 + s * 64 + pp;
#pragma unroll
        for (int j = 0; j < 4; j++)
            ct[gg * 256 + colTile + tc + j] = acc[i][j] + db[colTile + tc + j];
    }
}

// ---------------- elementwise / attention / LN kernels --------------------
__global__ void conv_hl(const float* __restrict__ s, __nv_bfloat16* __restrict__ h,
                        __nv_bfloat16* __restrict__ l, int n)
{
    int i = blockIdx.x * blockDim.x + threadIdx.x;
    if (i < n) wr_hl(h, l, i, s[i]);
}

__global__ void expand_tok(const float* __restrict__ op, const float* __restrict__ pe,
                           float* __restrict__ x0, __nv_bfloat16* __restrict__ xh,
                           __nv_bfloat16* __restrict__ xl)
{
    size_t i = (size_t)blockIdx.x * blockDim.x + threadIdx.x;
    int d = (int)(i & 255);
    int row = (int)(i >> 8);
    int p = row & 63;
    int bs = row >> 6;
    float v = op[bs * 256 + d] + pe[p * 256 + d];
    x0[i] = v; wr_hl(xh, xl, i, v);
}

__global__ void sa_attn(const float* __restrict__ qkv, __nv_bfloat16* __restrict__ oh,
                        __nv_bfloat16* __restrict__ ol)
{
    __shared__ float qs[64][64];
    __shared__ float kt[64][64];
    __shared__ float ss[64][64];
    int n = blockIdx.x, h = blockIdx.y;
    int tid = threadIdx.x;
    const float* base = qkv + (size_t)n * 64 * 768 + h * 64;
#pragma unroll
    for (int i = 0; i < 16; i++) {
        int e = tid + i * 256, l = e >> 6, d = e & 63;
        qs[l][d] = base[l * 768 + d];
        kt[d][(l + d) & 63] = base[l * 768 + 256 + d];
    }
    __syncthreads();
#pragma unroll
    for (int i = 0; i < 16; i++) {
        int e = tid + i * 256, r = e >> 6, c = e & 63;
        float acc = 0.0f;
#pragma unroll
        for (int d = 0; d < 64; d++) acc += qs[r][d] * kt[d][(c + d) & 63];
        ss[r][(c + r) & 63] = acc * 0.125f;
    }
    __syncthreads();
#pragma unroll
    for (int i = 0; i < 16; i++) {
        int e = tid + i * 256, l = e >> 6, d = e & 63;
        kt[d][(l + d) & 63] = base[l * 768 + 512 + d];
    }
    if (tid < 64) {
        int r = tid;
        float mx = -1e30f;
        for (int j = 0; j < 64; j++) mx = fmaxf(mx, ss[r][(j + r) & 63]);
        float sum = 0.0f;
        for (int j = 0; j < 64; j++) {
            float e = expf(ss[r][(j + r) & 63] - mx);
            ss[r][(j + r) & 63] = e; sum += e;
        }
        float inv = 1.0f / sum;
        for (int j = 0; j < 64; j++) ss[r][(j + r) & 63] *= inv;
    }
    __syncthreads();
#pragma unroll
    for (int i = 0; i < 16; i++) {
        int e = tid + i * 256, r = e >> 6, c = e & 63;
        float acc = 0.0f;
#pragma unroll
        for (int j = 0; j < 64; j++) acc += ss[r][(j + r) & 63] * kt[c][(j + c) & 63];
        wr_hl(oh, ol, ((size_t)n * 64 + r) * 256 + h * 64 + c, acc);
    }
}

__global__ void ln_res(const float* __restrict__ x1, int ld1,
                       const float* __restrict__ x2,
                       const float* __restrict__ g, const float* __restrict__ b,
                       float* __restrict__ out, __nv_bfloat16* __restrict__ oh,
                       __nv_bfloat16* __restrict__ ol, int M)
{
    int gw = (int)((blockIdx.x * (size_t)blockDim.x + threadIdx.x) >> 5);
    int lane = threadIdx.x & 31;
    if (gw >= M) return;
    const float* r1 = x1 + (size_t)gw * ld1;
    const float* r2 = x2 ? x2 + (size_t)gw * 256 : nullptr;
    float v[8];
    float s = 0.0f;
#pragma unroll
    for (int i = 0; i < 8; i++) {
        float t = r1[lane + i * 32];
        if (r2) t += r2[lane + i * 32];
        v[i] = t; s += t;
    }
#pragma unroll
    for (int o = 16; o; o >>= 1) s += __shfl_xor_sync(0xffffffffu, s, o);
    float mean = s * (1.0f / 256.0f);
    float var = 0.0f;
#pragma unroll
    for (int i = 0; i < 8; i++) { float d = v[i] - mean; var += d * d; }
#pragma unroll
    for (int o = 16; o; o >>= 1) var += __shfl_xor_sync(0xffffffffu, var, o);
    float rstd = rsqrtf(var * (1.0f / 256.0f) + 1e-5f);
#pragma unroll
    for (int i = 0; i < 8; i++) {
        int d = lane + i * 32;
        float y = (v[i] - mean) * rstd * g[d] + b[d];
        size_t o2 = (size_t)gw * 256 + d;
        if (out) out[o2] = y;
        if (oh) wr_hl(oh, ol, o2, y);
    }
}

__global__ void window_gather(const float* __restrict__ tok, float* __restrict__ x,
                              __nv_bfloat16* __restrict__ xh, __nv_bfloat16* __restrict__ xl)
{
    size_t i = (size_t)blockIdx.x * blockDim.x + threadIdx.x;
    int d = (int)(i & 255);
    int row = (int)(i >> 8);
    int c = row & 3;
    int seq = row >> 2;
    int p = seq & 63;
    int bs = seq >> 2 >> 4;  // seq >> 6
    int s = (seq >> 6) & 31;
    int b = seq >> 11;
    int sp = s + c - 3;
    float v = (sp < 0) ? 0.0f : tok[(((size_t)(b * 32 + sp) * 64 + p) << 8) + d];
    x[i] = v; wr_hl(xh, xl, i, v);
}

__global__ void ctx_attn(const float* __restrict__ qkv, __nv_bfloat16* __restrict__ oh,
                         __nv_bfloat16* __restrict__ ol, int last_only)
{
    int gw = (int)((blockIdx.x * (size_t)blockDim.x + threadIdx.x) >> 5);
    int lane = threadIdx.x & 31;
    int seq = gw >> 2, h = gw & 3;
    if (seq >= 16384) return;
    const float* base = qkv + (size_t)seq * 4 * 768 + h * 64;
    float k[4][2], v[4][2];
#pragma unroll
    for (int c = 0; c < 4; c++) {
        k[c][0] = base[c * 768 + 256 + lane];  k[c][1] = base[c * 768 + 256 + lane + 32];
        v[c][0] = base[c * 768 + 512 + lane];  v[c][1] = base[c * 768 + 512 + lane + 32];
    }
    if (last_only) {
        float q0 = base[3 * 768 + lane], q1 = base[3 * 768 + lane + 32];
        float p[4];
#pragma unroll
        for (int j = 0; j < 4; j++) {
            float s = q0 * k[j][0] + q1 * k[j][1];
#pragma unroll
            for (int o = 16; o; o >>= 1) s += __shfl_xor_sync(0xffffffffu, s, o);
            p[j] = s * 0.125f;
        }
        float mx = fmaxf(fmaxf(p[0], p[1]), fmaxf(p[2], p[3]));
        float e0 = expf(p[0] - mx), e1 = expf(p[1] - mx), e2 = expf(p[2] - mx), e3 = expf(p[3] - mx);
        float inv = 1.0f / (e0 + e1 + e2 + e3);
        p[0] = e0 * inv; p[1] = e1 * inv; p[2] = e2 * inv; p[3] = e3 * inv;
        float o0 = p[0] * v[0][0] + p[1] * v[1][0] + p[2] * v[2][0] + p[3] * v[3][0];
        float o1 = p[0] * v[0][1] + p[1] * v[1][1] + p[2] * v[2][1] + p[3] * v[3][1];
        wr_hl(oh, ol, (size_t)seq * 256 + h * 64 + lane, o0);
        wr_hl(oh, ol, (size_t)seq * 256 + h * 64 + lane + 32, o1);
    } else {
        float q[4][2];
#pragma unroll
        for (int c = 0; c < 4; c++) {
            q[c][0] = base[c * 768 + lane]; q[c][1] = base[c * 768 + lane + 32];
        }
        float p[4][4];
#pragma unroll
        for (int i = 0; i < 4; i++) {
#pragma unroll
            for (int j = 0; j < 4; j++) {
                float s = q[i][0] * k[j][0] + q[i][1] * k[j][1];
#pragma unroll
                for (int o = 16; o; o >>= 1) s += __shfl_xor_sync(0xffffffffu, s, o);
                p[i][j] = s * 0.125f;
            }
            float mx = fmaxf(fmaxf(p[i][0], p[i][1]), fmaxf(p[i][2], p[i][3]));
            float e0 = expf(p[i][0] - mx), e1 = expf(p[i][1] - mx);
            float e2 = expf(p[i][2] - mx), e3 = expf(p[i][3] - mx);
            float inv = 1.0f / (e0 + e1 + e2 + e3);
            p[i][0] = e0 * inv; p[i][1] = e1 * inv; p[i][2] = e2 * inv; p[i][3] = e3 * inv;
        }
#pragma unroll
        for (int i = 0; i < 4; i++) {
            float o0 = p[i][0] * v[0][0] + p[i][1] * v[1][0] + p[i][2] * v[2][0] + p[i][3] * v[3][0];
            float o1 = p[i][0] * v[0][1] + p[i][1] * v[1][1] + p[i][2] * v[2][1] + p[i][3] * v[3][1];
            size_t row = (size_t)seq * 4 + i;
            wr_hl(oh, ol, row * 256 + h * 64 + lane, o0);
            wr_hl(oh, ol, row * 256 + h * 64 + lane + 32, o1);
        }
    }
}

__global__ void copy_out0(const float* __restrict__ cur, float* __restrict__ ct)
{
    int i = blockIdx.x * blockDim.x + threadIdx.x;
    int d = i & 255; int m = i >> 8;
    int b = m >> 6, p = m & 63;
    size_t r = ((size_t)b * 2048 + p) * 256 + d;
    ct[r] = cur[r];
}

__global__ void cb_norms(const float* __restrict__ cb, float* __restrict__ cn)
{
    int gw = (int)((blockIdx.x * (size_t)blockDim.x + threadIdx.x) >> 5);
    int lane = threadIdx.x & 31;
    if (gw >= 1024) return;
    const float* r = cb + (size_t)gw * 256;
    float s = 0.0f;
#pragma unroll
    for (int i = 0; i < 8; i++) { float v = r[lane + i * 32]; s += v * v; }
#pragma unroll
    for (int o = 16; o; o >>= 1) s += __shfl_xor_sync(0xffffffffu, s, o);
    if (!lane) cn[gw] = s;
}

__global__ void vq_argmin(const float* __restrict__ x, const float* __restrict__ scores,
                          const float* __restrict__ cn, int* __restrict__ idx)
{
    int gw = (int)((blockIdx.x * (size_t)blockDim.x + threadIdx.x) >> 5);
    int lane = threadIdx.x & 31;
    if (gw >= 16384) return;
    const float* xr = x + (size_t)gw * 256;
    float xx = 0.0f;
#pragma unroll
    for (int i = 0; i < 8; i++) { float v = xr[lane + i * 32]; xx += v * v; }
#pragma unroll
    for (int o = 16; o; o >>= 1) xx += __shfl_xor_sync(0xffffffffu, xx, o);
    const float* sr = scores + (size_t)gw * 1024;
    float best = 3.4e38f; int bi = 0x7fffffff;
    for (int j = lane; j < 1024; j += 32) {
        float d = (xx - 2.0f * sr[j]) + cn[j];
        if (d < best || (d == best && j < bi)) { best = d; bi = j; }
    }
#pragma unroll
    for (int o = 16; o; o >>= 1) {
        float ob = __shfl_xor_sync(0xffffffffu, best, o);
        int   oi = __shfl_xor_sync(0xffffffffu, bi, o);
        if (ob < best || (ob == best && oi < bi)) { best = ob; bi = oi; }
    }
    if (!lane) idx[gw] = bi;
}

__global__ void mse_partial(const float* __restrict__ x, const float* __restrict__ cb,
                            const int* __restrict__ idx, float* __restrict__ red)
{
    __shared__ float sm[256];
    float s = 0.0f;
    size_t stride = (size_t)gridDim.x * blockDim.x;
    for (size_t i = (size_t)blockIdx.x * blockDim.x + threadIdx.x;
         i < (size_t)16384 * 256; i += stride) {
        int row = (int)(i >> 8), d = (int)(i & 255);
        float diff = x[i] - cb[(size_t)idx[row] * 256 + d];
        s += diff * diff;
    }
    sm[threadIdx.x] = s; __syncthreads();
    for (int o = 128; o; o >>= 1) {
        if ((int)threadIdx.x < o) sm[threadIdx.x] += sm[threadIdx.x + o];
        __syncthreads();
    }
    if (!threadIdx.x) red[blockIdx.x] = sm[0];
}

__global__ void mse_final(const float* __restrict__ red, float* __restrict__ out)
{
    __shared__ float sm[256];
    sm[threadIdx.x] = red[threadIdx.x]; __syncthreads();
    for (int o = 128; o; o >>= 1) {
        if ((int)threadIdx.x < o) sm[threadIdx.x] += sm[threadIdx.x + o];
        __syncthreads();
    }
    if (!threadIdx.x) {
        float mse = sm[0] / 4194304.0f;
        out[1064960] = 0.25f * mse;
        out[1064961] = mse;
        out[1064962] = 1.25f * mse;
    }
}

__global__ void idx_write(const int* __restrict__ idx, float* __restrict__ out)
{
    int i = blockIdx.x * blockDim.x + threadIdx.x;
    if (i < 16384) out[1048576 + i] = (float)idx[i];
}

// ---------------- host ----------------
static inline void* symp(const void* s)
{
    void* p = nullptr;
    cudaGetSymbolAddress(&p, s);
    return p;
}

extern "C" void kernel_launch(void* const* d_in, const int* in_sizes, int n_in,
                              void* d_out, int out_size)
{
    (void)in_sizes; (void)n_in; (void)out_size;
    const float* obs      = (const float*)d_in[0];
    const float* patch_w  = (const float*)d_in[2];
    const float* patch_b  = (const float*)d_in[3];
    const float* pos_emb  = (const float*)d_in[4];
    const float* sa_qkv_w = (const float*)d_in[5];
    const float* sa_qkv_b = (const float*)d_in[6];
    const float* sa_out_w = (const float*)d_in[7];
    const float* sa_out_b = (const float*)d_in[8];
    const float* sa_ln_g  = (const float*)d_in[9];
    const float* sa_ln_b  = (const float*)d_in[10];
    const float* cqkv_w   = (const float*)d_in[11];
    const float* cqkv_b   = (const float*)d_in[12];
    const float* cout_w   = (const float*)d_in[13];
    const float* cout_b   = (const float*)d_in[14];
    const float* cff1_w   = (const float*)d_in[15];
    const float* cff1_b   = (const float*)d_in[16];
    const float* cff2_w   = (const float*)d_in[17];
    const float* cff2_b   = (const float*)d_in[18];
    const float* cln1_g   = (const float*)d_in[19];
    const float* cln1_b   = (const float*)d_in[20];
    const float* cln2_g   = (const float*)d_in[21];
    const float* cln2_b   = (const float*)d_in[22];
    const float* delta_w  = (const float*)d_in[23];
    const float* delta_b  = (const float*)d_in[24];
    const float* codebook = (const float*)d_in[25];
    const float* dec_w1   = (const float*)d_in[26];
    const float* dec_b1   = (const float*)d_in[27];
    const float* dec_w2   = (const float*)d_in[28];
    const float* dec_b2   = (const float*)d_in[29];
    const float* dec_w3   = (const float*)d_in[30];
    const float* dec_b3   = (const float*)d_in[31];
    float* out = (float*)d_out;

    float* obsproj = (float*)symp(g_obsproj);
    float* x0      = (float*)symp(g_x0);
    float* qkv     = (float*)symp(g_qkv);
    float* proj    = (float*)symp(g_proj);
    float* tok     = (float*)symp(g_tok);
    float* xctx    = (float*)symp(g_xctx);
    float* hid     = (float*)symp(g_hid);
    float* xlast   = (float*)symp(g_xlast);
    float* cur     = (float*)symp(g_cur);
    float* ctxtok  = (float*)symp(g_ctxtok);
    float* cn      = (float*)symp(g_cn);
    float* red     = (float*)symp(g_red);
    int*   vidx    = (int*)symp(g_idx);
    __nv_bfloat16* x0h = (__nv_bfloat16*)symp(g_x0h);
    __nv_bfloat16* x0l = (__nv_bfloat16*)symp(g_x0l);
    __nv_bfloat16* ath = (__nv_bfloat16*)symp(g_ath);
    __nv_bfloat16* atl = (__nv_bfloat16*)symp(g_atl);
    __nv_bfloat16* xh  = (__nv_bfloat16*)symp(g_xh);
    __nv_bfloat16* xl  = (__nv_bfloat16*)symp(g_xl);
    __nv_bfloat16* hh  = (__nv_bfloat16*)symp(g_hh);
    __nv_bfloat16* hl  = (__nv_bfloat16*)symp(g_hl);
    __nv_bfloat16* xlh = (__nv_bfloat16*)symp(g_xlh);
    __nv_bfloat16* xll = (__nv_bfloat16*)symp(g_xll);
    __nv_bfloat16* cth = (__nv_bfloat16*)symp(g_cth);
    __nv_bfloat16* ctl = (__nv_bfloat16*)symp(g_ctl);
    __nv_bfloat16* wh  = (__nv_bfloat16*)symp(g_wh);
    __nv_bfloat16* wl  = (__nv_bfloat16*)symp(g_wl);

    // dynamic smem: 2 buffers * (2*128 + 2*NTILE) rows * 40 bf16 * 2B
    const int SM128 = 2 * (2 * 128 * 40 + 2 * 128 * 40) * 2;  // 81920
    const int SM64  = 2 * (2 * 128 * 40 + 2 * 64 * 40) * 2;   // 61440
    cudaFuncSetAttribute(gemm_mma<128>, cudaFuncAttributeMaxDynamicSharedMemorySize, SM128);
    cudaFuncSetAttribute(gemm_mma<64>,  cudaFuncAttributeMaxDynamicSharedMemorySize, SM64);

    const int T = 256;
    auto cv = [&](const float* src, int off, int n) {
        conv_hl<<<(n + 255) / 256, 256>>>(src, wh + off, wl + off, n);
    };
    cv(sa_qkv_w, OFF_SAQKV, 196608);
    cv(sa_out_w, OFF_SAOUT, 65536);
    cv(cqkv_w,            OFF_CQKV0, 196608);
    cv(cqkv_w + 196608,   OFF_CQKV1, 196608);
    cv(cout_w,            OFF_COUT0, 65536);
    cv(cout_w + 65536,    OFF_COUT1, 65536);
    cv(cff1_w,            OFF_FF1_0, 262144);
    cv(cff1_w + 262144,   OFF_FF1_1, 262144);
    cv(cff2_w,            OFF_FF2_0, 262144);
    cv(cff2_w + 262144,   OFF_FF2_1, 262144);
    cv(codebook,          OFF_CB,    262144);
    cv(dec_w1,            OFF_D1,    262144);
    cv(dec_w2,            OFF_D2,    1048576);
    cv(dec_w3,            OFF_D3,    65536);

    auto tc = [&](const __nv_bfloat16* Ah, const __nv_bfloat16* Al, int woff,
                  const float* bias, float* C, __nv_bfloat16* Chi, __nv_bfloat16* Clo,
                  int M, int N, int K, int relu, const int* Arows) {
        gemm_mma<128><<<dim3(N / 128, M / 128), 256, SM128>>>(
            Ah, Al, wh + woff, wl + woff, bias, C, Chi, Clo, N, K, relu, Arows);
    };

    // 1) patch projection + positional embed
    gemm_nt<<<dim3(4, 4), T>>>(obs, patch_w, patch_b, obsproj, 256, 256, 64);
    expand_tok<<<16384, T>>>(obsproj, pos_emb, x0, x0h, x0l);

    // 2) self-attention block
    tc(x0h, x0l, OFF_SAQKV, sa_qkv_b, qkv, nullptr, nullptr, 16384, 768, 256, 0, nullptr);
    sa_attn<<<dim3(256, 4), T>>>(qkv, ath, atl);
    tc(ath, atl, OFF_SAOUT, sa_out_b, proj, nullptr, nullptr, 16384, 256, 256, 0, nullptr);
    ln_res<<<2048, T>>>(proj, 256, x0, sa_ln_g, sa_ln_b, tok, nullptr, nullptr, 16384);

    // 3) windowed context gather
    window_gather<<<65536, T>>>(tok, xctx, xh, xl);

    // 4) context layer 0
    tc(xh, xl, OFF_CQKV0, cqkv_b, qkv, nullptr, nullptr, 65536, 768, 256, 0, nullptr);
    ctx_attn<<<8192, T>>>(qkv, ath, atl, 0);
    tc(ath, atl, OFF_COUT0, cout_b, proj, nullptr, nullptr, 65536, 256, 256, 0, nullptr);
    ln_res<<<8192, T>>>(xctx, 256, proj, cln1_g, cln1_b, xctx, xh, xl, 65536);
    tc(xh, xl, OFF_FF1_0, cff1_b, nullptr, hh, hl, 65536, 1024, 256, 1, nullptr);
    tc(hh, hl, OFF_FF2_0, cff2_b, proj, nullptr, nullptr, 65536, 256, 1024, 0, nullptr);
    ln_res<<<8192, T>>>(xctx, 256, proj, cln2_g, cln2_b, xctx, xh, xl, 65536);

    // 5) context layer 1 — only last position consumed downstream
    tc(xh, xl, OFF_CQKV1, cqkv_b + 768, qkv, nullptr, nullptr, 65536, 768, 256, 0, nullptr);
    ctx_attn<<<8192, T>>>(qkv, ath, atl, 1);
    tc(ath, atl, OFF_COUT1, cout_b + 256, proj, nullptr, nullptr, 16384, 256, 256, 0, nullptr);
    ln_res<<<2048, T>>>(xctx + 768, 1024, proj, cln1_g + 256, cln1_b + 256, xlast, xlh, xll, 16384);
    tc(xlh, xll, OFF_FF1_1, cff1_b + 1024, nullptr, hh, hl, 16384, 1024, 256, 1, nullptr);
    tc(hh, hl, OFF_FF2_1, cff2_b + 256, proj, nullptr, nullptr, 16384, 256, 1024, 0, nullptr);
    ln_res<<<2048, T>>>(xlast, 256, proj, cln2_g + 256, cln2_b + 256, cur, nullptr, nullptr, 16384);

    // 6) sequential delta scan
    copy_out0<<<512, T>>>(cur, ctxtok);
    for (int s = 1; s < 32; s++)
        gemm_scan<<<dim3(4, 8), T>>>(cur, delta_w, delta_b, ctxtok, s);
    conv_hl<<<16384, 256>>>(ctxtok, cth, ctl, 16384 * 256);

    // 7) VQ
    cb_norms<<<128, T>>>(codebook, cn);
    tc(cth, ctl, OFF_CB, nullptr, hid, nullptr, nullptr, 16384, 1024, 256, 0, nullptr);
    vq_argmin<<<2048, T>>>(ctxtok, hid, cn, vidx);

    // 8) losses + idx
    mse_partial<<<256, T>>>(ctxtok, codebook, vidx, red);
    mse_final<<<1, T>>>(red, out);
    idx_write<<<64, T>>>(vidx, out);

    // 9) decoder (A = codebook[idx] gathered in loader)
    tc(wh + OFF_CB, wl + OFF_CB, OFF_D1, dec_b1, nullptr, ath, atl, 16384, 1024, 256, 1, vidx);
    tc(ath, atl, OFF_D2, dec_b2, nullptr, xh, xl, 16384, 1024, 1024, 1, nullptr);
    gemm_mma<64><<<dim3(1, 128), 256, SM64>>>(
        xh, xl, wh + OFF_D3, wl + OFF_D3, dec_b3, out, nullptr, nullptr, 64, 1024, 0, nullptr);
}

// round 15
// speedup vs baseline: 2.4152x; 1.1331x over previous
#include <cuda_runtime.h>
#include <cuda_bf16.h>
#include <cuda_fp16.h>
#include <math.h>

// B=8 S=32 P=64 D=256 H=1024 K=1024 OBS=64 CTX=4 NH=4 dh=64

// ---------------- scratch ----------------
__device__ float g_obsproj[256 * 256];
__device__ float g_x0[16384 * 256];          // SA input; later layer-1 Q buffer
__device__ float g_qkv[65536 * 768];         // [0..12.6M) qkv_tok ; rest layer-1 KV
__device__ float g_proj[65536 * 256];
__device__ float g_tok[16384 * 256];
__device__ float g_xctx[65536 * 256];
__device__ float g_hid[16384 * 1024];
__device__ float g_xlast[16384 * 256];
__device__ float g_cur[16384 * 256];
__device__ float g_ctxtok[16384 * 256];
__device__ float g_cn[1024];
__device__ float g_red[256];
__device__ int   g_idx[16384];

__device__ unsigned short g_x0h[16384 * 256],  g_x0l[16384 * 256];
__device__ unsigned short g_tkh[16384 * 256],  g_tkl[16384 * 256];
__device__ unsigned short g_ath[65536 * 256],  g_atl[65536 * 256];
__device__ unsigned short g_xh [65536 * 256],  g_xl [65536 * 256];
__device__ unsigned short g_hh [65536 * 1024], g_hl [65536 * 1024];
__device__ unsigned short g_xlh[16384 * 256],  g_xll[16384 * 256];
__device__ unsigned short g_cth[16384 * 256],  g_ctl[16384 * 256];
__device__ unsigned short g_wh [2097152],      g_wl [2097152];   // bf16 weights
__device__ unsigned short g_fh [1638400],      g_fl [1638400];   // fp16 dec weights

#define OFF_SAQKV 0
#define OFF_SAOUT 196608
#define OFF_CQKV0 262144
#define OFF_CQKV1 458752
#define OFF_CKV1  524288
#define OFF_COUT0 655360
#define OFF_COUT1 720896
#define OFF_FF1_0 786432
#define OFF_FF1_1 1048576
#define OFF_FF2_0 1310720
#define OFF_FF2_1 1572864
#define OFF_CB    1835008
#define OFF_FD1   0
#define OFF_FD2   262144
#define OFF_FD3   1310720
#define OFF_FCB   1376256

// ---------------- PTX helpers ----------------
__device__ __forceinline__ unsigned smem_u32(const void* p) {
    unsigned a;
    asm("{ .reg .u64 t; cvta.to.shared.u64 t, %1; cvt.u32.u64 %0, t; }"
        : "=r"(a) : "l"(p));
    return a;
}
__device__ __forceinline__ void cpa16(unsigned s, const void* g) {
    asm volatile("cp.async.cg.shared.global [%0], [%1], 16;" :: "r"(s), "l"(g) : "memory");
}
__device__ __forceinline__ void cp_commit() {
    asm volatile("cp.async.commit_group;" ::: "memory");
}
template <int N> __device__ __forceinline__ void cp_wait() {
    asm volatile("cp.async.wait_group %0;" :: "n"(N) : "memory");
}
__device__ __forceinline__ void ldsm4(unsigned& r0, unsigned& r1, unsigned& r2,
                                      unsigned& r3, unsigned a) {
    asm volatile("ldmatrix.sync.aligned.m8n8.x4.shared.b16 {%0,%1,%2,%3}, [%4];"
                 : "=r"(r0), "=r"(r1), "=r"(r2), "=r"(r3) : "r"(a));
}
__device__ __forceinline__ void ldsm2(unsigned& r0, unsigned& r1, unsigned a) {
    asm volatile("ldmatrix.sync.aligned.m8n8.x2.shared.b16 {%0,%1}, [%2];"
                 : "=r"(r0), "=r"(r1) : "r"(a));
}
__device__ __forceinline__ void mma_bf(float* d, const unsigned* a, const unsigned* b) {
    asm volatile("mma.sync.aligned.m16n8k16.row.col.f32.bf16.bf16.f32 "
                 "{%0,%1,%2,%3},{%4,%5,%6,%7},{%8,%9},{%0,%1,%2,%3};"
                 : "+f"(d[0]), "+f"(d[1]), "+f"(d[2]), "+f"(d[3])
                 : "r"(a[0]), "r"(a[1]), "r"(a[2]), "r"(a[3]), "r"(b[0]), "r"(b[1]));
}
__device__ __forceinline__ void mma_fp(float* d, const unsigned* a, const unsigned* b) {
    asm volatile("mma.sync.aligned.m16n8k16.row.col.f32.f16.f16.f32 "
                 "{%0,%1,%2,%3},{%4,%5,%6,%7},{%8,%9},{%0,%1,%2,%3};"
                 : "+f"(d[0]), "+f"(d[1]), "+f"(d[2]), "+f"(d[3])
                 : "r"(a[0]), "r"(a[1]), "r"(a[2]), "r"(a[3]), "r"(b[0]), "r"(b[1]));
}
__device__ __forceinline__ void wr_hl(unsigned short* h, unsigned short* l,
                                      size_t i, float v) {
    __nv_bfloat16 hh = __float2bfloat16(v);
    h[i] = __bfloat16_as_ushort(hh);
    l[i] = __bfloat16_as_ushort(__float2bfloat16(v - __bfloat162float(hh)));
}
__device__ __forceinline__ unsigned pack_bf(float a, float b, unsigned& lo) {
    __nv_bfloat16 h0 = __float2bfloat16(a), h1 = __float2bfloat16(b);
    lo = (unsigned)__bfloat16_as_ushort(__float2bfloat16(a - __bfloat162float(h0))) |
         ((unsigned)__bfloat16_as_ushort(__float2bfloat16(b - __bfloat162float(h1))) << 16);
    return (unsigned)__bfloat16_as_ushort(h0) | ((unsigned)__bfloat16_as_ushort(h1) << 16);
}
__device__ __forceinline__ unsigned pack_fp(float a, float b, unsigned& lo) {
    __half h0 = __float2half(a), h1 = __float2half(b);
    lo = (unsigned)__half_as_ushort(__float2half(a - __half2float(h0))) |
         ((unsigned)__half_as_ushort(__float2half(b - __half2float(h1))) << 16);
    return (unsigned)__half_as_ushort(h0) | ((unsigned)__half_as_ushort(h1) << 16);
}

// ---------------- HMMA split GEMM: C = A @ W^T (+bias)(+relu) -------------
// row map: gr = rowTile+r; if Arows gr=Arows[gr]; gr = gr*amul+aadd
template <int NTILE, int NMMA, bool F16>
__global__ __launch_bounds__(256, 1) void gemm_mma(
    const unsigned short* __restrict__ Ah, const unsigned short* __restrict__ Al,
    const unsigned short* __restrict__ Wh, const unsigned short* __restrict__ Wl,
    const float* __restrict__ bias, float* __restrict__ C,
    unsigned short* __restrict__ Chi, unsigned short* __restrict__ Clo,
    int N, int K, int relu, const int* __restrict__ Arows, int amul, int aadd)
{
    constexpr int LDS = 40;
    constexpr int ASZ = 128 * LDS;
    constexpr int WSZ = NTILE * LDS;
    constexpr int BUF = 2 * ASZ + 2 * WSZ;
    constexpr int WN  = NTILE / 4;
    constexpr int NI  = WN / 8;
    extern __shared__ unsigned short sm[];
    const unsigned sb = smem_u32(sm);
    const int tid = threadIdx.x;
    const int wid = tid >> 5, lane = tid & 31;
    const int rowTile = blockIdx.y * 128;
    const int colTile = blockIdx.x * NTILE;
    const int wm = (wid >> 2) * 64;
    const int wn = (wid & 3) * WN;

    const int nchunk = K >> 5;
    auto load_chunk = [&](int c) {
        const unsigned base = sb + (unsigned)(c & 1) * BUF * 2;
        const int k0 = c << 5;
        for (int i = tid; i < 512; i += 256) {
            int r = i >> 2, cc = (i & 3) << 3;
            int gr = rowTile + r;
            if (Arows) gr = Arows[gr];
            gr = gr * amul + aadd;
            size_t go = (size_t)gr * K + k0 + cc;
            unsigned sa = base + (unsigned)(r * LDS + cc) * 2;
            cpa16(sa, Ah + go);
            if (NMMA == 3) cpa16(sa + ASZ * 2, Al + go);
        }
        for (int i = tid; i < NTILE * 4; i += 256) {
            int r = i >> 2, cc = (i & 3) << 3;
            size_t go = (size_t)(colTile + r) * K + k0 + cc;
            unsigned sa = base + (unsigned)(2 * ASZ + r * LDS + cc) * 2;
            cpa16(sa, Wh + go);
            cpa16(sa + WSZ * 2, Wl + go);
        }
    };

    float acc[4][NI][4];
#pragma unroll
    for (int mi = 0; mi < 4; mi++)
#pragma unroll
        for (int ni = 0; ni < NI; ni++)
#pragma unroll
            for (int j = 0; j < 4; j++) acc[mi][ni][j] = 0.0f;

    load_chunk(0); cp_commit();
    for (int c = 0; c < nchunk; c++) {
        if (c + 1 < nchunk) { load_chunk(c + 1); cp_commit(); cp_wait<1>(); }
        else cp_wait<0>();
        __syncthreads();
        const unsigned base = sb + (unsigned)(c & 1) * BUF * 2;
#pragma unroll
        for (int ks = 0; ks < 2; ks++) {
            const int kof  = ks * 16 + ((lane >> 4) & 1) * 8;
            const int kof2 = ks * 16 + ((lane >> 3) & 1) * 8;
            unsigned ah[4][4], al[4][4], bh[NI][2], bl[NI][2];
#pragma unroll
            for (int mi = 0; mi < 4; mi++) {
                unsigned a = base + (unsigned)((wm + mi * 16 + (lane & 15)) * LDS + kof) * 2;
                ldsm4(ah[mi][0], ah[mi][1], ah[mi][2], ah[mi][3], a);
                if (NMMA == 3)
                    ldsm4(al[mi][0], al[mi][1], al[mi][2], al[mi][3], a + ASZ * 2);
            }
#pragma unroll
            for (int ni = 0; ni < NI; ni++) {
                unsigned a = base + (unsigned)(2 * ASZ + (wn + ni * 8 + (lane & 7)) * LDS + kof2) * 2;
                ldsm2(bh[ni][0], bh[ni][1], a);
                ldsm2(bl[ni][0], bl[ni][1], a + WSZ * 2);
            }
#pragma unroll
            for (int mi = 0; mi < 4; mi++)
#pragma unroll
                for (int ni = 0; ni < NI; ni++) {
                    if (F16) {
                        mma_fp(acc[mi][ni], ah[mi], bh[ni]);
                        mma_fp(acc[mi][ni], ah[mi], bl[ni]);
                        if (NMMA == 3) mma_fp(acc[mi][ni], al[mi], bh[ni]);
                    } else {
                        mma_bf(acc[mi][ni], ah[mi], bh[ni]);
                        mma_bf(acc[mi][ni], ah[mi], bl[ni]);
                        if (NMMA == 3) mma_bf(acc[mi][ni], al[mi], bh[ni]);
                    }
                }
        }
        __syncthreads();
    }

    const int rbase = rowTile + wm + (lane >> 2);
    const int cbase = colTile + wn + 2 * (lane & 3);
#pragma unroll
    for (int mi = 0; mi < 4; mi++) {
#pragma unroll
        for (int ni = 0; ni < NI; ni++) {
            int cc = cbase + ni * 8;
            float b0 = bias ? bias[cc] : 0.0f;
            float b1 = bias ? bias[cc + 1] : 0.0f;
#pragma unroll
            for (int half = 0; half < 2; half++) {
                int r = rbase + mi * 16 + half * 8;
                float v0 = acc[mi][ni][half * 2 + 0] + b0;
                float v1 = acc[mi][ni][half * 2 + 1] + b1;
                if (relu) { v0 = fmaxf(v0, 0.0f); v1 = fmaxf(v1, 0.0f); }
                size_t o = (size_t)r * N + cc;
                if (C) *(float2*)(C + o) = make_float2(v0, v1);
                if (Chi) {
                    unsigned lo, hi;
                    if (F16) hi = pack_fp(v0, v1, lo);
                    else     hi = pack_bf(v0, v1, lo);
                    *(unsigned*)(Chi + o) = hi;
                    *(unsigned*)(Clo + o) = lo;
                }
            }
        }
    }
}

// ---------------- fp32 NT gemm (patch proj) ----------------
__global__ void gemm_nt(const float* __restrict__ A, const float* __restrict__ W,
                        const float* __restrict__ bias, float* __restrict__ C,
                        int M, int N, int K)
{
    __shared__ float As[16][64];
    __shared__ float Ws[16][64];
    const int tid = threadIdx.x;
    const int rowTile = blockIdx.y * 64, colTile = blockIdx.x * 64;
    const int lr = tid >> 2, lc = (tid & 3) << 2;
    const int tr = (tid >> 4) << 2, tc = (tid & 15) << 2;
    const float* Aptr = A + (size_t)(rowTile + lr) * K + lc;
    const float* Wptr = W + (size_t)(colTile + lr) * K + lc;
    float acc[4][4] = {};
    for (int k0 = 0; k0 < K; k0 += 16) {
        float4 av = *(const float4*)(Aptr + k0);
        float4 wv = *(const float4*)(Wptr + k0);
        As[lc + 0][lr] = av.x; As[lc + 1][lr] = av.y; As[lc + 2][lr] = av.z; As[lc + 3][lr] = av.w;
        Ws[lc + 0][lr] = wv.x; Ws[lc + 1][lr] = wv.y; Ws[lc + 2][lr] = wv.z; Ws[lc + 3][lr] = wv.w;
        __syncthreads();
#pragma unroll
        for (int k = 0; k < 16; k++) {
            float4 a = *(const float4*)(&As[k][tr]);
            float4 b = *(const float4*)(&Ws[k][tc]);
            acc[0][0] += a.x * b.x; acc[0][1] += a.x * b.y; acc[0][2] += a.x * b.z; acc[0][3] += a.x * b.w;
            acc[1][0] += a.y * b.x; acc[1][1] += a.y * b.y; acc[1][2] += a.y * b.z; acc[1][3] += a.y * b.w;
            acc[2][0] += a.z * b.x; acc[2][1] += a.z * b.y; acc[2][2] += a.z * b.z; acc[2][3] += a.z * b.w;
            acc[3][0] += a.w * b.x; acc[3][1] += a.w * b.y; acc[3][2] += a.w * b.z; acc[3][3] += a.w * b.w;
        }
        __syncthreads();
    }
#pragma unroll
    for (int i = 0; i < 4; i++)
#pragma unroll
        for (int j = 0; j < 4; j++)
            C[(size_t)(rowTile + tr + i) * N + colTile + tc + j] =
                acc[i][j] + (bias ? bias[colTile + tc + j] : 0.0f);
}

// ---------------- per-step scan gemm (proven in 3676us baseline) ----------
__global__ void gemm_scan(const float* __restrict__ cur, const float* __restrict__ dw,
                          const float* __restrict__ db, float* __restrict__ ct, int s)
{
    __shared__ float As[16][64];
    __shared__ float Ws[16][64];
    const int tid = threadIdx.x;
    const int rowTile = blockIdx.y * 64;
    const int colTile = blockIdx.x * 64;
    const int lr = tid >> 2, lc = (tid & 3) << 2;
    const int tr = (tid >> 4) << 2, tc = (tid & 15) << 2;
    int m = lr + rowTile;
    int b = m >> 6, p = m & 63;
    size_t g = (size_t)b * 2048 + s * 64 + p;
    const float* crow = cur + g * 256;
    const float* prow = ct + (g - 64) * 256;
    const float* Wptr = dw + (size_t)(colTile + lr) * 512 + lc;
    float acc[4][4] = {};
    for (int k0 = 0; k0 < 512; k0 += 16) {
        int kk = k0 + lc;
        float4 av;
        if (kk < 256) av = *(const float4*)(crow + kk);
        else {
            float4 a = *(const float4*)(crow + kk - 256);
            float4 q = *(const float4*)(prow + kk - 256);
            av = make_float4(a.x - q.x, a.y - q.y, a.z - q.z, a.w - q.w);
        }
        float4 wv = *(const float4*)(Wptr + k0);
        As[lc + 0][lr] = av.x; As[lc + 1][lr] = av.y; As[lc + 2][lr] = av.z; As[lc + 3][lr] = av.w;
        Ws[lc + 0][lr] = wv.x; Ws[lc + 1][lr] = wv.y; Ws[lc + 2][lr] = wv.z; Ws[lc + 3][lr] = wv.w;
        __syncthreads();
#pragma unroll
        for (int k = 0; k < 16; k++) {
            float4 a = *(const float4*)(&As[k][tr]);
            float4 bb = *(const float4*)(&Ws[k][tc]);
            acc[0][0] += a.x * bb.x; acc[0][1] += a.x * bb.y; acc[0][2] += a.x * bb.z; acc[0][3] += a.x * bb.w;
            acc[1][0] += a.y * bb.x; acc[1][1] += a.y * bb.y; acc[1][2] += a.y * bb.z; acc[1][3] += a.y * bb.w;
            acc[2][0] += a.z * bb.x; acc[2][1] += a.z * bb.y; acc[2][2] += a.z * bb.z; acc[2][3] += a.z * bb.w;
            acc[3][0] += a.w * bb.x; acc[3][1] += a.w * bb.y; acc[3][2] += a.w * bb.z; acc[3][3] += a.w * bb.w;
        }
        __syncthreads();
    }
#pragma unroll
    for (int i = 0; i < 4; i++) {
        int mm = rowTile + tr + i;
        int bb2 = mm >> 6, pp = mm & 63;
        size_t gg = (size_t)bb2 * 2048 + s * 64 + pp;
#pragma unroll
        for (int j = 0; j < 4; j++)
            ct[gg * 256 + colTile + tc + j] = acc[i][j] + db[colTile + tc + j];
    }
}

__global__ void copy_out0(const float* __restrict__ cur, float* __restrict__ ct)
{
    int i = blockIdx.x * blockDim.x + threadIdx.x;
    int d = i & 255; int m = i >> 8;
    int b = m >> 6, p = m & 63;
    size_t r = ((size_t)b * 2048 + p) * 256 + d;
    ct[r] = cur[r];
}

// ---------------- batched hi/lo conversion ----------------
struct ConvSeg { const float* src; long off; };
struct ConvTab { ConvSeg s[12]; long cum[13]; int cnt; };
__global__ void conv_batch(ConvTab t, unsigned short* __restrict__ h,
                           unsigned short* __restrict__ l, int f16, long total)
{
    long i = (long)blockIdx.x * blockDim.x + threadIdx.x;
    if (i >= total) return;
    int k = 0;
    while (k + 1 < t.cnt && i >= t.cum[k + 1]) k++;
    long j = i - t.cum[k];
    float v = t.s[k].src[j];
    long d = t.s[k].off + j;
    if (f16) {
        __half hh = __float2half(v);
        h[d] = __half_as_ushort(hh);
        l[d] = __half_as_ushort(__float2half(v - __half2float(hh)));
    } else {
        __nv_bfloat16 hh = __float2bfloat16(v);
        h[d] = __bfloat16_as_ushort(hh);
        l[d] = __bfloat16_as_ushort(__float2bfloat16(v - __bfloat162float(hh)));
    }
}
__global__ void conv_hl(const float* __restrict__ s, unsigned short* __restrict__ h,
                        unsigned short* __restrict__ l, int n)
{
    int i = blockIdx.x * blockDim.x + threadIdx.x;
    if (i < n) wr_hl(h, l, i, s[i]);
}

// ---------------- elementwise / attention / LN ----------------
__global__ void expand_tok(const float* __restrict__ op, const float* __restrict__ pe,
                           float* __restrict__ x0, unsigned short* __restrict__ xh,
                           unsigned short* __restrict__ xl)
{
    size_t i = (size_t)blockIdx.x * blockDim.x + threadIdx.x;
    int d = (int)(i & 255), row = (int)(i >> 8);
    float v = op[(row >> 6) * 256 + d] + pe[(row & 63) * 256 + d];
    x0[i] = v; wr_hl(xh, xl, i, v);
}

__global__ void sa_attn(const float* __restrict__ qkv, unsigned short* __restrict__ oh,
                        unsigned short* __restrict__ ol)
{
    __shared__ float qs[64][64];
    __shared__ float kt[64][64];
    __shared__ float sc[64][64];
    int n = blockIdx.x, h = blockIdx.y, tid = threadIdx.x;
    const float* base = qkv + (size_t)n * 64 * 768 + h * 64;
#pragma unroll
    for (int i = 0; i < 16; i++) {
        int e = tid + i * 256, l = e >> 6, d = e & 63;
        qs[l][d] = base[l * 768 + d];
        kt[d][(l + d) & 63] = base[l * 768 + 256 + d];
    }
    __syncthreads();
#pragma unroll
    for (int i = 0; i < 16; i++) {
        int e = tid + i * 256, r = e >> 6, c = e & 63;
        float acc = 0.0f;
#pragma unroll
        for (int d = 0; d < 64; d++) acc += qs[r][d] * kt[d][(c + d) & 63];
        sc[r][(c + r) & 63] = acc * 0.125f;
    }
    __syncthreads();
#pragma unroll
    for (int i = 0; i < 16; i++) {
        int e = tid + i * 256, l = e >> 6, d = e & 63;
        kt[d][(l + d) & 63] = base[l * 768 + 512 + d];
    }
    if (tid < 64) {
        int r = tid;
        float mx = -1e30f;
        for (int j = 0; j < 64; j++) mx = fmaxf(mx, sc[r][(j + r) & 63]);
        float sum = 0.0f;
        for (int j = 0; j < 64; j++) {
            float e = expf(sc[r][(j + r) & 63] - mx);
            sc[r][(j + r) & 63] = e; sum += e;
        }
        float inv = 1.0f / sum;
        for (int j = 0; j < 64; j++) sc[r][(j + r) & 63] *= inv;
    }
    __syncthreads();
#pragma unroll
    for (int i = 0; i < 16; i++) {
        int e = tid + i * 256, r = e >> 6, c = e & 63;
        float acc = 0.0f;
#pragma unroll
        for (int j = 0; j < 64; j++) acc += sc[r][(j + r) & 63] * kt[c][(j + c) & 63];
        wr_hl(oh, ol, ((size_t)n * 64 + r) * 256 + h * 64 + c, acc);
    }
}

// x2mode: 0 none, 1 direct, 2 windowed gather over tok
__global__ void ln_res(const float* __restrict__ x1, int ld1,
                       const float* __restrict__ x2, int x2mode,
                       const float* __restrict__ g, const float* __restrict__ b,
                       float* __restrict__ out, unsigned short* __restrict__ oh,
                       unsigned short* __restrict__ ol, int M)
{
    int gw = (int)((blockIdx.x * (size_t)blockDim.x + threadIdx.x) >> 5);
    int lane = threadIdx.x & 31;
    if (gw >= M) return;
    const float* r1 = x1 + (size_t)gw * ld1;
    const float* r2 = nullptr;
    if (x2mode == 1) r2 = x2 + (size_t)gw * 256;
    else if (x2mode == 2) {
        int c = gw & 3, p = (gw >> 2) & 63, s = (gw >> 8) & 31, bb = gw >> 13;
        int sp = s + c - 3;
        if (sp >= 0) r2 = x2 + (size_t)((bb * 32 + sp) * 64 + p) * 256;
    }
    float v[8], sum = 0.0f;
#pragma unroll
    for (int i = 0; i < 8; i++) {
        float t = r1[lane + i * 32];
        if (r2) t += r2[lane + i * 32];
        v[i] = t; sum += t;
    }
#pragma unroll
    for (int o = 16; o; o >>= 1) sum += __shfl_xor_sync(0xffffffffu, sum, o);
    float mean = sum * (1.0f / 256.0f), var = 0.0f;
#pragma unroll
    for (int i = 0; i < 8; i++) { float d = v[i] - mean; var += d * d; }
#pragma unroll
    for (int o = 16; o; o >>= 1) var += __shfl_xor_sync(0xffffffffu, var, o);
    float rstd = rsqrtf(var * (1.0f / 256.0f) + 1e-5f);
#pragma unroll
    for (int i = 0; i < 8; i++) {
        int d = lane + i * 32;
        float y = (v[i] - mean) * rstd * g[d] + b[d];
        size_t o2 = (size_t)gw * 256 + d;
        if (out) out[o2] = y;
        if (oh) wr_hl(oh, ol, o2, y);
    }
}

// layer-0 ctx attn: qkv of unique tokens, window gather, bias for pad rows
__global__ void ctx_attn0(const float* __restrict__ qkvt, const float* __restrict__ qb,
                          unsigned short* __restrict__ oh, unsigned short* __restrict__ ol)
{
    int gw = (int)((blockIdx.x * (size_t)blockDim.x + threadIdx.x) >> 5);
    int lane = threadIdx.x & 31;
    int seq = gw >> 2, h = gw & 3;
    if (seq >= 16384) return;
    int b = seq >> 11, s = (seq >> 6) & 31, p = seq & 63;
    float q[4][2], k[4][2], v[4][2];
#pragma unroll
    for (int c = 0; c < 4; c++) {
        int sp = s + c - 3;
        const float* row = (sp >= 0)
            ? qkvt + (size_t)((b * 32 + sp) * 64 + p) * 768 + h * 64 : nullptr;
        if (row) {
            q[c][0] = row[lane];       q[c][1] = row[lane + 32];
            k[c][0] = row[256 + lane]; k[c][1] = row[256 + lane + 32];
            v[c][0] = row[512 + lane]; v[c][1] = row[512 + lane + 32];
        } else {
            q[c][0] = qb[h * 64 + lane];       q[c][1] = qb[h * 64 + lane + 32];
            k[c][0] = qb[256 + h * 64 + lane]; k[c][1] = qb[256 + h * 64 + lane + 32];
            v[c][0] = qb[512 + h * 64 + lane]; v[c][1] = qb[512 + h * 64 + lane + 32];
        }
    }
    float pm[4][4];
#pragma unroll
    for (int i = 0; i < 4; i++) {
#pragma unroll
        for (int j = 0; j < 4; j++) {
            float t = q[i][0] * k[j][0] + q[i][1] * k[j][1];
#pragma unroll
            for (int o = 16; o; o >>= 1) t += __shfl_xor_sync(0xffffffffu, t, o);
            pm[i][j] = t * 0.125f;
        }
        float mx = fmaxf(fmaxf(pm[i][0], pm[i][1]), fmaxf(pm[i][2], pm[i][3]));
        float e0 = expf(pm[i][0] - mx), e1 = expf(pm[i][1] - mx);
        float e2 = expf(pm[i][2] - mx), e3 = expf(pm[i][3] - mx);
        float inv = 1.0f / (e0 + e1 + e2 + e3);
        pm[i][0] = e0 * inv; pm[i][1] = e1 * inv; pm[i][2] = e2 * inv; pm[i][3] = e3 * inv;
    }
#pragma unroll
    for (int i = 0; i < 4; i++) {
        float o0 = pm[i][0] * v[0][0] + pm[i][1] * v[1][0] + pm[i][2] * v[2][0] + pm[i][3] * v[3][0];
        float o1 = pm[i][0] * v[0][1] + pm[i][1] * v[1][1] + pm[i][2] * v[2][1] + pm[i][3] * v[3][1];
        size_t row = (size_t)seq * 4 + i;
        wr_hl(oh, ol, row * 256 + h * 64 + lane, o0);
        wr_hl(oh, ol, row * 256 + h * 64 + lane + 32, o1);
    }
}

// layer-1 ctx attn: separate Q (last pos only) and KV buffers
__global__ void ctx_attn1(const float* __restrict__ qbuf, const float* __restrict__ kv,
                          unsigned short* __restrict__ oh, unsigned short* __restrict__ ol)
{
    int gw = (int)((blockIdx.x * (size_t)blockDim.x + threadIdx.x) >> 5);
    int lane = threadIdx.x & 31;
    int seq = gw >> 2, h = gw & 3;
    if (seq >= 16384) return;
    float q0 = qbuf[(size_t)seq * 256 + h * 64 + lane];
    float q1 = qbuf[(size_t)seq * 256 + h * 64 + lane + 32];
    float k[4][2], v[4][2], pr[4];
#pragma unroll
    for (int c = 0; c < 4; c++) {
        const float* base = kv + (size_t)(seq * 4 + c) * 512 + h * 64;
        k[c][0] = base[lane];       k[c][1] = base[lane + 32];
        v[c][0] = base[256 + lane]; v[c][1] = base[256 + lane + 32];
    }
#pragma unroll
    for (int j = 0; j < 4; j++) {
        float t = q0 * k[j][0] + q1 * k[j][1];
#pragma unroll
        for (int o = 16; o; o >>= 1) t += __shfl_xor_sync(0xffffffffu, t, o);
        pr[j] = t * 0.125f;
    }
    float mx = fmaxf(fmaxf(pr[0], pr[1]), fmaxf(pr[2], pr[3]));
    float e0 = expf(pr[0] - mx), e1 = expf(pr[1] - mx), e2 = expf(pr[2] - mx), e3 = expf(pr[3] - mx);
    float inv = 1.0f / (e0 + e1 + e2 + e3);
    pr[0] = e0 * inv; pr[1] = e1 * inv; pr[2] = e2 * inv; pr[3] = e3 * inv;
    float o0 = pr[0] * v[0][0] + pr[1] * v[1][0] + pr[2] * v[2][0] + pr[3] * v[3][0];
    float o1 = pr[0] * v[0][1] + pr[1] * v[1][1] + pr[2] * v[2][1] + pr[3] * v[3][1];
    wr_hl(oh, ol, (size_t)seq * 256 + h * 64 + lane, o0);
    wr_hl(oh, ol, (size_t)seq * 256 + h * 64 + lane + 32, o1);
}

// ---------------- VQ / losses ----------------
__global__ void cb_norms(const float* __restrict__ cb, float* __restrict__ cn)
{
    int gw = (int)((blockIdx.x * (size_t)blockDim.x + threadIdx.x) >> 5);
    int lane = threadIdx.x & 31;
    if (gw >= 1024) return;
    const float* r = cb + (size_t)gw * 256;
    float s = 0.0f;
#pragma unroll
    for (int i = 0; i < 8; i++) { float v = r[lane + i * 32]; s += v * v; }
#pragma unroll
    for (int o = 16; o; o >>= 1) s += __shfl_xor_sync(0xffffffffu, s, o);
    if (!lane) cn[gw] = s;
}

__global__ void vq_argmin(const float* __restrict__ x, const float* __restrict__ scores,
                          const float* __restrict__ cn, int* __restrict__ idx)
{
    int gw = (int)((blockIdx.x * (size_t)blockDim.x + threadIdx.x) >> 5);
    int lane = threadIdx.x & 31;
    if (gw >= 16384) return;
    const float* xr = x + (size_t)gw * 256;
    float xx = 0.0f;
#pragma unroll
    for (int i = 0; i < 8; i++) { float v = xr[lane + i * 32]; xx += v * v; }
#pragma unroll
    for (int o = 16; o; o >>= 1) xx += __shfl_xor_sync(0xffffffffu, xx, o);
    const float* sr = scores + (size_t)gw * 1024;
    float best = 3.4e38f; int bi = 0x7fffffff;
    for (int j = lane; j < 1024; j += 32) {
        float d = (xx - 2.0f * sr[j]) + cn[j];
        if (d < best || (d == best && j < bi)) { best = d; bi = j; }
    }
#pragma unroll
    for (int o = 16; o; o >>= 1) {
        float ob = __shfl_xor_sync(0xffffffffu, best, o);
        int   oi = __shfl_xor_sync(0xffffffffu, bi, o);
        if (ob < best || (ob == best && oi < bi)) { best = ob; bi = oi; }
    }
    if (!lane) idx[gw] = bi;
}

__global__ void mse_partial(const float* __restrict__ x, const float* __restrict__ cb,
                            const int* __restrict__ idx, float* __restrict__ red)
{
    __shared__ float sm[256];
    float s = 0.0f;
    size_t stride = (size_t)gridDim.x * blockDim.x;
    for (size_t i = (size_t)blockIdx.x * blockDim.x + threadIdx.x;
         i < (size_t)16384 * 256; i += stride) {
        int row = (int)(i >> 8), d = (int)(i & 255);
        float diff = x[i] - cb[(size_t)idx[row] * 256 + d];
        s += diff * diff;
    }
    sm[threadIdx.x] = s; __syncthreads();
    for (int o = 128; o; o >>= 1) {
        if ((int)threadIdx.x < o) sm[threadIdx.x] += sm[threadIdx.x + o];
        __syncthreads();
    }
    if (!threadIdx.x) red[blockIdx.x] = sm[0];
}

__global__ void mse_final(const float* __restrict__ red, float* __restrict__ out)
{
    __shared__ float sm[256];
    sm[threadIdx.x] = red[threadIdx.x]; __syncthreads();
    for (int o = 128; o; o >>= 1) {
        if ((int)threadIdx.x < o) sm[threadIdx.x] += sm[threadIdx.x + o];
        __syncthreads();
    }
    if (!threadIdx.x) {
        float mse = sm[0] / 4194304.0f;
        out[1064960] = 0.25f * mse;
        out[1064961] = mse;
        out[1064962] = 1.25f * mse;
    }
}

__global__ void idx_write(const int* __restrict__ idx, float* __restrict__ out)
{
    int i = blockIdx.x * blockDim.x + threadIdx.x;
    if (i < 16384) out[1048576 + i] = (float)idx[i];
}

// ---------------- host ----------------
static inline void* symp(const void* s)
{
    void* p = nullptr;
    cudaGetSymbolAddress(&p, s);
    return p;
}

extern "C" void kernel_launch(void* const* d_in, const int* in_sizes, int n_in,
                              void* d_out, int out_size)
{
    (void)in_sizes; (void)n_in; (void)out_size;
    const float* obs      = (const float*)d_in[0];
    const float* patch_w  = (const float*)d_in[2];
    const float* patch_b  = (const float*)d_in[3];
    const float* pos_emb  = (const float*)d_in[4];
    const float* sa_qkv_w = (const float*)d_in[5];
    const float* sa_qkv_b = (const float*)d_in[6];
    const float* sa_out_w = (const float*)d_in[7];
    const float* sa_out_b = (const float*)d_in[8];
    const float* sa_ln_g  = (const float*)d_in[9];
    const float* sa_ln_b  = (const float*)d_in[10];
    const float* cqkv_w   = (const float*)d_in[11];
    const float* cqkv_b   = (const float*)d_in[12];
    const float* cout_w   = (const float*)d_in[13];
    const float* cout_b   = (const float*)d_in[14];
    const float* cff1_w   = (const float*)d_in[15];
    const float* cff1_b   = (const float*)d_in[16];
    const float* cff2_w   = (const float*)d_in[17];
    const float* cff2_b   = (const float*)d_in[18];
    const float* cln1_g   = (const float*)d_in[19];
    const float* cln1_b   = (const float*)d_in[20];
    const float* cln2_g   = (const float*)d_in[21];
    const float* cln2_b   = (const float*)d_in[22];
    const float* delta_w  = (const float*)d_in[23];
    const float* delta_b  = (const float*)d_in[24];
    const float* codebook = (const float*)d_in[25];
    const float* dec_w1   = (const float*)d_in[26];
    const float* dec_b1   = (const float*)d_in[27];
    const float* dec_w2   = (const float*)d_in[28];
    const float* dec_b2   = (const float*)d_in[29];
    const float* dec_w3   = (const float*)d_in[30];
    const float* dec_b3   = (const float*)d_in[31];
    float* out = (float*)d_out;

    float* obsproj = (float*)symp(g_obsproj);
    float* x0      = (float*)symp(g_x0);
    float* qkv     = (float*)symp(g_qkv);
    float* kvbuf   = qkv + (size_t)16384 * 768;
    float* proj    = (float*)symp(g_proj);
    float* tok     = (float*)symp(g_tok);
    float* xctx    = (float*)symp(g_xctx);
    float* hid     = (float*)symp(g_hid);
    float* xlast   = (float*)symp(g_xlast);
    float* cur     = (float*)symp(g_cur);
    float* ctxtok  = (float*)symp(g_ctxtok);
    float* cn      = (float*)symp(g_cn);
    float* red     = (float*)symp(g_red);
    int*   vidx    = (int*)symp(g_idx);
    unsigned short* x0h = (unsigned short*)symp(g_x0h);
    unsigned short* x0l = (unsigned short*)symp(g_x0l);
    unsigned short* tkh = (unsigned short*)symp(g_tkh);
    unsigned short* tkl = (unsigned short*)symp(g_tkl);
    unsigned short* ath = (unsigned short*)symp(g_ath);
    unsigned short* atl = (unsigned short*)symp(g_atl);
    unsigned short* xh  = (unsigned short*)symp(g_xh);
    unsigned short* xl  = (unsigned short*)symp(g_xl);
    unsigned short* hh  = (unsigned short*)symp(g_hh);
    unsigned short* hl  = (unsigned short*)symp(g_hl);
    unsigned short* xlh = (unsigned short*)symp(g_xlh);
    unsigned short* xll = (unsigned short*)symp(g_xll);
    unsigned short* cth = (unsigned short*)symp(g_cth);
    unsigned short* ctl = (unsigned short*)symp(g_ctl);
    unsigned short* wh  = (unsigned short*)symp(g_wh);
    unsigned short* wl  = (unsigned short*)symp(g_wl);
    unsigned short* fh  = (unsigned short*)symp(g_fh);
    unsigned short* fl  = (unsigned short*)symp(g_fl);

    const int SM128 = 2 * (2 * 128 * 40 + 2 * 128 * 40) * 2;
    const int SM64  = 2 * (2 * 128 * 40 + 2 * 64 * 40) * 2;
    cudaFuncSetAttribute(gemm_mma<128, 3, false>, cudaFuncAttributeMaxDynamicSharedMemorySize, SM128);
    cudaFuncSetAttribute(gemm_mma<128, 2, true>,  cudaFuncAttributeMaxDynamicSharedMemorySize, SM128);
    cudaFuncSetAttribute(gemm_mma<64, 2, true>,   cudaFuncAttributeMaxDynamicSharedMemorySize, SM64);

    const int T = 256;

    // batched weight conversions (bf16 pool, fp16 pool)
    {
        ConvTab tb = {};
        const float* srcs[11] = { sa_qkv_w, sa_out_w, cqkv_w, cqkv_w + 196608,
                                  cout_w, cout_w + 65536, cff1_w, cff1_w + 262144,
                                  cff2_w, cff2_w + 262144, codebook };
        long offs[11] = { OFF_SAQKV, OFF_SAOUT, OFF_CQKV0, OFF_CQKV1, OFF_COUT0,
                          OFF_COUT1, OFF_FF1_0, OFF_FF1_1, OFF_FF2_0, OFF_FF2_1, OFF_CB };
        long ns[11] = { 196608, 65536, 196608, 196608, 65536, 65536,
                        262144, 262144, 262144, 262144, 262144 };
        long cum = 0;
        for (int i = 0; i < 11; i++) {
            tb.s[i].src = srcs[i]; tb.s[i].off = offs[i];
            tb.cum[i] = cum; cum += ns[i];
        }
        tb.cum[11] = cum; tb.cnt = 11;
        conv_batch<<<(int)((cum + 255) / 256), 256>>>(tb, wh, wl, 0, cum);

        ConvTab tf = {};
        const float* fsrcs[4] = { dec_w1, dec_w2, dec_w3, codebook };
        long foffs[4] = { OFF_FD1, OFF_FD2, OFF_FD3, OFF_FCB };
        long fns[4] = { 262144, 1048576, 65536, 262144 };
        cum = 0;
        for (int i = 0; i < 4; i++) {
            tf.s[i].src = fsrcs[i]; tf.s[i].off = foffs[i];
            tf.cum[i] = cum; cum += fns[i];
        }
        tf.cum[4] = cum; tf.cnt = 4;
        conv_batch<<<(int)((cum + 255) / 256), 256>>>(tf, fh, fl, 1, cum);
    }

    auto G = [&](const unsigned short* Ah, const unsigned short* Al, int woff,
                 const float* bias, float* C, unsigned short* Chi, unsigned short* Clo,
                 int M, int N, int K, int relu, const int* Arows, int amul, int aadd) {
        gemm_mma<128, 3, false><<<dim3(N / 128, M / 128), 256, SM128>>>(
            Ah, Al, wh + woff, wl + woff, bias, C, Chi, Clo, N, K, relu, Arows, amul, aadd);
    };
    auto Gf = [&](const unsigned short* Ah, const unsigned short* Al, int woff,
                  const float* bias, unsigned short* Chi, unsigned short* Clo,
                  int M, int N, int K, int relu, const int* Arows) {
        gemm_mma<128, 2, true><<<dim3(N / 128, M / 128), 256, SM128>>>(
            Ah, Al, fh + woff, fl + woff, bias, nullptr, Chi, Clo, N, K, relu, Arows, 1, 0);
    };

    // 1) patch projection + positional embed
    gemm_nt<<<dim3(4, 4), T>>>(obs, patch_w, patch_b, obsproj, 256, 256, 64);
    expand_tok<<<16384, T>>>(obsproj, pos_emb, x0, x0h, x0l);

    // 2) self-attention block
    G(x0h, x0l, OFF_SAQKV, sa_qkv_b, qkv, nullptr, nullptr, 16384, 768, 256, 0, nullptr, 1, 0);
    sa_attn<<<dim3(256, 4), T>>>(qkv, ath, atl);
    G(ath, atl, OFF_SAOUT, sa_out_b, proj, nullptr, nullptr, 16384, 256, 256, 0, nullptr, 1, 0);
    ln_res<<<2048, T>>>(proj, 256, x0, 1, sa_ln_g, sa_ln_b, tok, tkh, tkl, 16384);

    // 3) context layer 0: qkv on unique tokens, attention gathers window
    G(tkh, tkl, OFF_CQKV0, cqkv_b, qkv, nullptr, nullptr, 16384, 768, 256, 0, nullptr, 1, 0);
    ctx_attn0<<<8192, T>>>(qkv, cqkv_b, ath, atl);
    G(ath, atl, OFF_COUT0, cout_b, proj, nullptr, nullptr, 65536, 256, 256, 0, nullptr, 1, 0);
    ln_res<<<8192, T>>>(proj, 256, tok, 2, cln1_g, cln1_b, xctx, xh, xl, 65536);
    G(xh, xl, OFF_FF1_0, cff1_b, nullptr, hh, hl, 65536, 1024, 256, 1, nullptr, 1, 0);
    G(hh, hl, OFF_FF2_0, cff2_b, proj, nullptr, nullptr, 65536, 256, 1024, 0, nullptr, 1, 0);
    ln_res<<<8192, T>>>(xctx, 256, proj, 1, cln2_g, cln2_b, xctx, xh, xl, 65536);

    // 4) context layer 1: KV for all rows, Q only at last position (4i+3)
    G(xh, xl, OFF_CKV1, cqkv_b + 768 + 256, kvbuf, nullptr, nullptr, 65536, 512, 256, 0, nullptr, 1, 0);
    G(xh, xl, OFF_CQKV1, cqkv_b + 768, x0, nullptr, nullptr, 16384, 256, 256, 0, nullptr, 4, 3);
    ctx_attn1<<<8192, T>>>(x0, kvbuf, ath, atl);
    G(ath, atl, OFF_COUT1, cout_b + 256, proj, nullptr, nullptr, 16384, 256, 256, 0, nullptr, 1, 0);
    ln_res<<<2048, T>>>(xctx + 768, 1024, proj, 1, cln1_g + 256, cln1_b + 256, xlast, xlh, xll, 16384);
    G(xlh, xll, OFF_FF1_1, cff1_b + 1024, nullptr, hh, hl, 16384, 1024, 256, 1, nullptr, 1, 0);
    G(hh, hl, OFF_FF2_1, cff2_b + 256, proj, nullptr, nullptr, 16384, 256, 1024, 0, nullptr, 1, 0);
    ln_res<<<2048, T>>>(xlast, 256, proj, 1, cln2_g + 256, cln2_b + 256, cur, nullptr, nullptr, 16384);

    // 5) sequential delta scan (proven per-step kernels)
    copy_out0<<<512, T>>>(cur, ctxtok);
    for (int s = 1; s < 32; s++)
        gemm_scan<<<dim3(4, 8), T>>>(cur, delta_w, delta_b, ctxtok, s);
    conv_hl<<<16384, T>>>(ctxtok, cth, ctl, 16384 * 256);

    // 6) VQ
    cb_norms<<<128, T>>>(codebook, cn);
    G(cth, ctl, OFF_CB, nullptr, hid, nullptr, nullptr, 16384, 1024, 256, 0, nullptr, 1, 0);
    vq_argmin<<<2048, T>>>(ctxtok, hid, cn, vidx);

    // 7) losses + idx
    mse_partial<<<256, T>>>(ctxtok, codebook, vidx, red);
    mse_final<<<1, T>>>(red, out);
    idx_write<<<64, T>>>(vidx, out);

    // 8) decoder (fp16 hi/lo, 2-MMA split; A = codebook[idx] gathered)
    Gf(fh + OFF_FCB, fl + OFF_FCB, OFF_FD1, dec_b1, ath, atl, 16384, 1024, 256, 1, vidx);
    Gf(ath, atl, OFF_FD2, dec_b2, xh, xl, 16384, 1024, 1024, 1, nullptr);
    gemm_mma<64, 2, true><<<dim3(1, 128), 256, SM64>>>(
        xh, xl, fh + OFF_FD3, fl + OFF_FD3, dec_b3, out, nullptr, nullptr,
        64, 1024, 0, nullptr, 1, 0);
}

// round 16
// speedup vs baseline: 3.0532x; 1.2642x over previous
#include <cuda_runtime.h>
#include <cuda_bf16.h>
#include <cuda_fp16.h>
#include <math.h>

// B=8 S=32 P=64 D=256 H=1024 K=1024 OBS=64 CTX=4 NH=4 dh=64

// ---------------- scratch ----------------
__device__ float g_obsproj[256 * 256];       // patch proj; later W1+W2 scratch
__device__ float g_x0[16384 * 256];
__device__ float g_qkv[65536 * 768];
__device__ float g_proj[65536 * 256];
__device__ float g_tok[16384 * 256];
__device__ float g_xctx[65536 * 256];
__device__ float g_hid[16384 * 1024];        // scan Acc, later VQ scores
__device__ float g_xlast[16384 * 256];
__device__ float g_cur[16384 * 256];
__device__ float g_ctxtok[16384 * 256];
__device__ float g_cn[1024];
__device__ float g_red[256];
__device__ int   g_idx[16384];

__device__ unsigned short g_x0h[16384 * 256],  g_x0l[16384 * 256];
__device__ unsigned short g_tkh[16384 * 256],  g_tkl[16384 * 256];
__device__ unsigned short g_ath[65536 * 256],  g_atl[65536 * 256];
__device__ unsigned short g_xh [65536 * 256],  g_xl [65536 * 256];
__device__ unsigned short g_hh [65536 * 1024], g_hl [65536 * 1024];
__device__ unsigned short g_xlh[16384 * 256],  g_xll[16384 * 256];
__device__ unsigned short g_cth[16384 * 256],  g_ctl[16384 * 256];
__device__ unsigned short g_wsh[65536],        g_wsl[65536];        // W1+W2 hi/lo
__device__ unsigned short g_wh [2097152],      g_wl [2097152];
__device__ unsigned short g_fh [1638400],      g_fl [1638400];

#define OFF_SAQKV 0
#define OFF_SAOUT 196608
#define OFF_CQKV0 262144
#define OFF_CQKV1 458752
#define OFF_CKV1  524288
#define OFF_COUT0 655360
#define OFF_COUT1 720896
#define OFF_FF1_0 786432
#define OFF_FF1_1 1048576
#define OFF_FF2_0 1310720
#define OFF_FF2_1 1572864
#define OFF_CB    1835008
#define OFF_FD1   0
#define OFF_FD2   262144
#define OFF_FD3   1310720
#define OFF_FCB   1376256

// ---------------- PTX helpers ----------------
__device__ __forceinline__ unsigned smem_u32(const void* p) {
    unsigned a;
    asm("{ .reg .u64 t; cvta.to.shared.u64 t, %1; cvt.u32.u64 %0, t; }"
        : "=r"(a) : "l"(p));
    return a;
}
__device__ __forceinline__ void cpa16(unsigned s, const void* g) {
    asm volatile("cp.async.cg.shared.global [%0], [%1], 16;" :: "r"(s), "l"(g) : "memory");
}
__device__ __forceinline__ void cp_commit() {
    asm volatile("cp.async.commit_group;" ::: "memory");
}
template <int N> __device__ __forceinline__ void cp_wait() {
    asm volatile("cp.async.wait_group %0;" :: "n"(N) : "memory");
}
__device__ __forceinline__ void ldsm4(unsigned& r0, unsigned& r1, unsigned& r2,
                                      unsigned& r3, unsigned a) {
    asm volatile("ldmatrix.sync.aligned.m8n8.x4.shared.b16 {%0,%1,%2,%3}, [%4];"
                 : "=r"(r0), "=r"(r1), "=r"(r2), "=r"(r3) : "r"(a));
}
__device__ __forceinline__ void ldsm2(unsigned& r0, unsigned& r1, unsigned a) {
    asm volatile("ldmatrix.sync.aligned.m8n8.x2.shared.b16 {%0,%1}, [%2];"
                 : "=r"(r0), "=r"(r1) : "r"(a));
}
__device__ __forceinline__ void mma_bf(float* d, const unsigned* a, const unsigned* b) {
    asm volatile("mma.sync.aligned.m16n8k16.row.col.f32.bf16.bf16.f32 "
                 "{%0,%1,%2,%3},{%4,%5,%6,%7},{%8,%9},{%0,%1,%2,%3};"
                 : "+f"(d[0]), "+f"(d[1]), "+f"(d[2]), "+f"(d[3])
                 : "r"(a[0]), "r"(a[1]), "r"(a[2]), "r"(a[3]), "r"(b[0]), "r"(b[1]));
}
__device__ __forceinline__ void mma_fp(float* d, const unsigned* a, const unsigned* b) {
    asm volatile("mma.sync.aligned.m16n8k16.row.col.f32.f16.f16.f32 "
                 "{%0,%1,%2,%3},{%4,%5,%6,%7},{%8,%9},{%0,%1,%2,%3};"
                 : "+f"(d[0]), "+f"(d[1]), "+f"(d[2]), "+f"(d[3])
                 : "r"(a[0]), "r"(a[1]), "r"(a[2]), "r"(a[3]), "r"(b[0]), "r"(b[1]));
}
__device__ __forceinline__ void wr_hl(unsigned short* h, unsigned short* l,
                                      size_t i, float v) {
    __nv_bfloat16 hh = __float2bfloat16(v);
    h[i] = __bfloat16_as_ushort(hh);
    l[i] = __bfloat16_as_ushort(__float2bfloat16(v - __bfloat162float(hh)));
}
__device__ __forceinline__ unsigned pack_bf(float a, float b, unsigned& lo) {
    __nv_bfloat16 h0 = __float2bfloat16(a), h1 = __float2bfloat16(b);
    lo = (unsigned)__bfloat16_as_ushort(__float2bfloat16(a - __bfloat162float(h0))) |
         ((unsigned)__bfloat16_as_ushort(__float2bfloat16(b - __bfloat162float(h1))) << 16);
    return (unsigned)__bfloat16_as_ushort(h0) | ((unsigned)__bfloat16_as_ushort(h1) << 16);
}
__device__ __forceinline__ unsigned pack_fp(float a, float b, unsigned& lo) {
    __half h0 = __float2half(a), h1 = __float2half(b);
    lo = (unsigned)__half_as_ushort(__float2half(a - __half2float(h0))) |
         ((unsigned)__half_as_ushort(__float2half(b - __half2float(h1))) << 16);
    return (unsigned)__half_as_ushort(h0) | ((unsigned)__half_as_ushort(h1) << 16);
}

// ---------------- HMMA split GEMM: C = A @ W^T (+bias)(+relu) -------------
// Per-mi fragment loading keeps live regs < 128 so 2 CTAs/SM fit.
template <int NTILE, int NMMA, bool F16>
__global__ __launch_bounds__(256, 2) void gemm_mma(
    const unsigned short* __restrict__ Ah, const unsigned short* __restrict__ Al,
    const unsigned short* __restrict__ Wh, const unsigned short* __restrict__ Wl,
    const float* __restrict__ bias, float* __restrict__ C,
    unsigned short* __restrict__ Chi, unsigned short* __restrict__ Clo,
    int N, int K, int relu, const int* __restrict__ Arows, int amul, int aadd)
{
    constexpr int LDS = 40;
    constexpr int ASZ = 128 * LDS;
    constexpr int WSZ = NTILE * LDS;
    constexpr int BUF = 2 * ASZ + 2 * WSZ;
    constexpr int WN  = NTILE / 4;
    constexpr int NI  = WN / 8;
    extern __shared__ unsigned short sm[];
    const unsigned sb = smem_u32(sm);
    const int tid = threadIdx.x;
    const int wid = tid >> 5, lane = tid & 31;
    const int rowTile = blockIdx.y * 128;
    const int colTile = blockIdx.x * NTILE;
    const int wm = (wid >> 2) * 64;
    const int wn = (wid & 3) * WN;

    const int nchunk = K >> 5;
    auto load_chunk = [&](int c) {
        const unsigned base = sb + (unsigned)(c & 1) * BUF * 2;
        const int k0 = c << 5;
        for (int i = tid; i < 512; i += 256) {
            int r = i >> 2, cc = (i & 3) << 3;
            int gr = rowTile + r;
            if (Arows) gr = Arows[gr];
            gr = gr * amul + aadd;
            size_t go = (size_t)gr * K + k0 + cc;
            unsigned sa = base + (unsigned)(r * LDS + cc) * 2;
            cpa16(sa, Ah + go);
            if (NMMA == 3) cpa16(sa + ASZ * 2, Al + go);
        }
        for (int i = tid; i < NTILE * 4; i += 256) {
            int r = i >> 2, cc = (i & 3) << 3;
            size_t go = (size_t)(colTile + r) * K + k0 + cc;
            unsigned sa = base + (unsigned)(2 * ASZ + r * LDS + cc) * 2;
            cpa16(sa, Wh + go);
            cpa16(sa + WSZ * 2, Wl + go);
        }
    };

    float acc[4][NI][4];
#pragma unroll
    for (int mi = 0; mi < 4; mi++)
#pragma unroll
        for (int ni = 0; ni < NI; ni++)
#pragma unroll
            for (int j = 0; j < 4; j++) acc[mi][ni][j] = 0.0f;

    load_chunk(0); cp_commit();
    for (int c = 0; c < nchunk; c++) {
        if (c + 1 < nchunk) { load_chunk(c + 1); cp_commit(); cp_wait<1>(); }
        else cp_wait<0>();
        __syncthreads();
        const unsigned base = sb + (unsigned)(c & 1) * BUF * 2;
#pragma unroll
        for (int ks = 0; ks < 2; ks++) {
            const int kof  = ks * 16 + ((lane >> 4) & 1) * 8;
            const int kof2 = ks * 16 + ((lane >> 3) & 1) * 8;
            unsigned bh[NI][2], bl[NI][2];
#pragma unroll
            for (int ni = 0; ni < NI; ni++) {
                unsigned a = base + (unsigned)(2 * ASZ + (wn + ni * 8 + (lane & 7)) * LDS + kof2) * 2;
                ldsm2(bh[ni][0], bh[ni][1], a);
                ldsm2(bl[ni][0], bl[ni][1], a + WSZ * 2);
            }
#pragma unroll
            for (int mi = 0; mi < 4; mi++) {
                unsigned aadr = base + (unsigned)((wm + mi * 16 + (lane & 15)) * LDS + kof) * 2;
                unsigned a[4];
                ldsm4(a[0], a[1], a[2], a[3], aadr);
#pragma unroll
                for (int ni = 0; ni < NI; ni++) {
                    if (F16) { mma_fp(acc[mi][ni], a, bh[ni]); mma_fp(acc[mi][ni], a, bl[ni]); }
                    else     { mma_bf(acc[mi][ni], a, bh[ni]); mma_bf(acc[mi][ni], a, bl[ni]); }
                }
                if (NMMA == 3) {
                    ldsm4(a[0], a[1], a[2], a[3], aadr + ASZ * 2);
#pragma unroll
                    for (int ni = 0; ni < NI; ni++) {
                        if (F16) mma_fp(acc[mi][ni], a, bh[ni]);
                        else     mma_bf(acc[mi][ni], a, bh[ni]);
                    }
                }
            }
        }
        __syncthreads();
    }

    const int rbase = rowTile + wm + (lane >> 2);
    const int cbase = colTile + wn + 2 * (lane & 3);
#pragma unroll
    for (int mi = 0; mi < 4; mi++) {
#pragma unroll
        for (int ni = 0; ni < NI; ni++) {
            int cc = cbase + ni * 8;
            float b0 = bias ? bias[cc] : 0.0f;
            float b1 = bias ? bias[cc + 1] : 0.0f;
#pragma unroll
            for (int half = 0; half < 2; half++) {
                int r = rbase + mi * 16 + half * 8;
                float v0 = acc[mi][ni][half * 2 + 0] + b0;
                float v1 = acc[mi][ni][half * 2 + 1] + b1;
                if (relu) { v0 = fmaxf(v0, 0.0f); v1 = fmaxf(v1, 0.0f); }
                size_t o = (size_t)r * N + cc;
                if (C) *(float2*)(C + o) = make_float2(v0, v1);
                if (Chi) {
                    unsigned lo, hi;
                    if (F16) hi = pack_fp(v0, v1, lo);
                    else     hi = pack_bf(v0, v1, lo);
                    *(unsigned*)(Chi + o) = hi;
                    *(unsigned*)(Clo + o) = lo;
                }
            }
        }
    }
}

// ---------------- fp32 NT gemm (patch proj) ----------------
__global__ void gemm_nt(const float* __restrict__ A, const float* __restrict__ W,
                        const float* __restrict__ bias, float* __restrict__ C,
                        int M, int N, int K)
{
    __shared__ float As[16][64];
    __shared__ float Ws[16][64];
    const int tid = threadIdx.x;
    const int rowTile = blockIdx.y * 64, colTile = blockIdx.x * 64;
    const int lr = tid >> 2, lc = (tid & 3) << 2;
    const int tr = (tid >> 4) << 2, tc = (tid & 15) << 2;
    const float* Aptr = A + (size_t)(rowTile + lr) * K + lc;
    const float* Wptr = W + (size_t)(colTile + lr) * K + lc;
    float acc[4][4] = {};
    for (int k0 = 0; k0 < K; k0 += 16) {
        float4 av = *(const float4*)(Aptr + k0);
        float4 wv = *(const float4*)(Wptr + k0);
        As[lc + 0][lr] = av.x; As[lc + 1][lr] = av.y; As[lc + 2][lr] = av.z; As[lc + 3][lr] = av.w;
        Ws[lc + 0][lr] = wv.x; Ws[lc + 1][lr] = wv.y; Ws[lc + 2][lr] = wv.z; Ws[lc + 3][lr] = wv.w;
        __syncthreads();
#pragma unroll
        for (int k = 0; k < 16; k++) {
            float4 a = *(const float4*)(&As[k][tr]);
            float4 b = *(const float4*)(&Ws[k][tc]);
            acc[0][0] += a.x * b.x; acc[0][1] += a.x * b.y; acc[0][2] += a.x * b.z; acc[0][3] += a.x * b.w;
            acc[1][0] += a.y * b.x; acc[1][1] += a.y * b.y; acc[1][2] += a.y * b.z; acc[1][3] += a.y * b.w;
            acc[2][0] += a.z * b.x; acc[2][1] += a.z * b.y; acc[2][2] += a.z * b.z; acc[2][3] += a.z * b.w;
            acc[3][0] += a.w * b.x; acc[3][1] += a.w * b.y; acc[3][2] += a.w * b.z; acc[3][3] += a.w * b.w;
        }
        __syncthreads();
    }
#pragma unroll
    for (int i = 0; i < 4; i++)
#pragma unroll
        for (int j = 0; j < 4; j++)
            C[(size_t)(rowTile + tr + i) * N + colTile + tc + j] =
                acc[i][j] + (bias ? bias[colTile + tc + j] : 0.0f);
}

// ---------------- scan: W1+W2 precombine ----------------
__global__ void wsum_make(const float* __restrict__ dw, float* __restrict__ ws)
{
    int i = blockIdx.x * blockDim.x + threadIdx.x;  // 65536
    int n = i >> 8, k = i & 255;
    ws[i] = dw[n * 512 + k] + dw[n * 512 + 256 + k];
}

// scan step: ct[g] = Acc[g] - ct[g-64] @ W2^T   (K=256, 64x64 tiles)
__global__ void gemm_scan2(const float* __restrict__ accb, const float* __restrict__ dw2,
                           float* __restrict__ ct, int s)
{
    __shared__ float As[16][64];
    __shared__ float Ws[16][64];
    const int tid = threadIdx.x;
    const int rowTile = blockIdx.y * 64;
    const int colTile = blockIdx.x * 64;
    const int lr = tid >> 2, lc = (tid & 3) << 2;
    const int tr = (tid >> 4) << 2, tc = (tid & 15) << 2;
    int m = rowTile + lr;
    int b = m >> 6, p = m & 63;
    const float* Aptr = ct + ((size_t)b * 2048 + (s - 1) * 64 + p) * 256 + lc;
    const float* Wptr = dw2 + (size_t)(colTile + lr) * 512 + lc;
    float acc[4][4] = {};
    for (int k0 = 0; k0 < 256; k0 += 16) {
        float4 av = *(const float4*)(Aptr + k0);
        float4 wv = *(const float4*)(Wptr + k0);
        As[lc + 0][lr] = av.x; As[lc + 1][lr] = av.y; As[lc + 2][lr] = av.z; As[lc + 3][lr] = av.w;
        Ws[lc + 0][lr] = wv.x; Ws[lc + 1][lr] = wv.y; Ws[lc + 2][lr] = wv.z; Ws[lc + 3][lr] = wv.w;
        __syncthreads();
#pragma unroll
        for (int k = 0; k < 16; k++) {
            float4 a = *(const float4*)(&As[k][tr]);
            float4 bb = *(const float4*)(&Ws[k][tc]);
            acc[0][0] += a.x * bb.x; acc[0][1] += a.x * bb.y; acc[0][2] += a.x * bb.z; acc[0][3] += a.x * bb.w;
            acc[1][0] += a.y * bb.x; acc[1][1] += a.y * bb.y; acc[1][2] += a.y * bb.z; acc[1][3] += a.y * bb.w;
            acc[2][0] += a.z * bb.x; acc[2][1] += a.z * bb.y; acc[2][2] += a.z * bb.z; acc[2][3] += a.z * bb.w;
            acc[3][0] += a.w * bb.x; acc[3][1] += a.w * bb.y; acc[3][2] += a.w * bb.z; acc[3][3] += a.w * bb.w;
        }
        __syncthreads();
    }
#pragma unroll
    for (int i = 0; i < 4; i++) {
        int mm = rowTile + tr + i;
        int bb2 = mm >> 6, pp = mm & 63;
        size_t g = (size_t)bb2 * 2048 + s * 64 + pp;
#pragma unroll
        for (int j = 0; j < 4; j++) {
            int cc = colTile + tc + j;
            ct[g * 256 + cc] = accb[g * 256 + cc] - acc[i][j];
        }
    }
}

__global__ void copy_out0(const float* __restrict__ cur, float* __restrict__ ct)
{
    int i = blockIdx.x * blockDim.x + threadIdx.x;
    int d = i & 255; int m = i >> 8;
    int b = m >> 6, p = m & 63;
    size_t r = ((size_t)b * 2048 + p) * 256 + d;
    ct[r] = cur[r];
}

// ---------------- batched hi/lo conversion ----------------
struct ConvSeg { const float* src; long off; };
struct ConvTab { ConvSeg s[12]; long cum[13]; int cnt; };
__global__ void conv_batch(ConvTab t, unsigned short* __restrict__ h,
                           unsigned short* __restrict__ l, int f16, long total)
{
    long i = (long)blockIdx.x * blockDim.x + threadIdx.x;
    if (i >= total) return;
    int k = 0;
    while (k + 1 < t.cnt && i >= t.cum[k + 1]) k++;
    long j = i - t.cum[k];
    float v = t.s[k].src[j];
    long d = t.s[k].off + j;
    if (f16) {
        __half hh = __float2half(v);
        h[d] = __half_as_ushort(hh);
        l[d] = __half_as_ushort(__float2half(v - __half2float(hh)));
    } else {
        __nv_bfloat16 hh = __float2bfloat16(v);
        h[d] = __bfloat16_as_ushort(hh);
        l[d] = __bfloat16_as_ushort(__float2bfloat16(v - __bfloat162float(hh)));
    }
}
__global__ void conv_hl(const float* __restrict__ s, unsigned short* __restrict__ h,
                        unsigned short* __restrict__ l, int n)
{
    int i = blockIdx.x * blockDim.x + threadIdx.x;
    if (i < n) wr_hl(h, l, i, s[i]);
}

// ---------------- elementwise / attention / LN ----------------
__global__ void expand_tok(const float* __restrict__ op, const float* __restrict__ pe,
                           float* __restrict__ x0, unsigned short* __restrict__ xh,
                           unsigned short* __restrict__ xl)
{
    size_t i = (size_t)blockIdx.x * blockDim.x + threadIdx.x;
    int d = (int)(i & 255), row = (int)(i >> 8);
    float v = op[(row >> 6) * 256 + d] + pe[(row & 63) * 256 + d];
    x0[i] = v; wr_hl(xh, xl, i, v);
}

__global__ void sa_attn(const float* __restrict__ qkv, unsigned short* __restrict__ oh,
                        unsigned short* __restrict__ ol)
{
    __shared__ float qs[64][64];
    __shared__ float kt[64][64];
    __shared__ float sc[64][64];
    int n = blockIdx.x, h = blockIdx.y, tid = threadIdx.x;
    const float* base = qkv + (size_t)n * 64 * 768 + h * 64;
#pragma unroll
    for (int i = 0; i < 16; i++) {
        int e = tid + i * 256, l = e >> 6, d = e & 63;
        qs[l][d] = base[l * 768 + d];
        kt[d][(l + d) & 63] = base[l * 768 + 256 + d];
    }
    __syncthreads();
#pragma unroll
    for (int i = 0; i < 16; i++) {
        int e = tid + i * 256, r = e >> 6, c = e & 63;
        float acc = 0.0f;
#pragma unroll
        for (int d = 0; d < 64; d++) acc += qs[r][d] * kt[d][(c + d) & 63];
        sc[r][(c + r) & 63] = acc * 0.125f;
    }
    __syncthreads();
#pragma unroll
    for (int i = 0; i < 16; i++) {
        int e = tid + i * 256, l = e >> 6, d = e & 63;
        kt[d][(l + d) & 63] = base[l * 768 + 512 + d];
    }
    if (tid < 64) {
        int r = tid;
        float mx = -1e30f;
        for (int j = 0; j < 64; j++) mx = fmaxf(mx, sc[r][(j + r) & 63]);
        float sum = 0.0f;
        for (int j = 0; j < 64; j++) {
            float e = expf(sc[r][(j + r) & 63] - mx);
            sc[r][(j + r) & 63] = e; sum += e;
        }
        float inv = 1.0f / sum;
        for (int j = 0; j < 64; j++) sc[r][(j + r) & 63] *= inv;
    }
    __syncthreads();
#pragma unroll
    for (int i = 0; i < 16; i++) {
        int e = tid + i * 256, r = e >> 6, c = e & 63;
        float acc = 0.0f;
#pragma unroll
        for (int j = 0; j < 64; j++) acc += sc[r][(j + r) & 63] * kt[c][(j + c) & 63];
        wr_hl(oh, ol, ((size_t)n * 64 + r) * 256 + h * 64 + c, acc);
    }
}

// x2mode: 0 none, 1 direct, 2 windowed gather over tok
__global__ void ln_res(const float* __restrict__ x1, int ld1,
                       const float* __restrict__ x2, int x2mode,
                       const float* __restrict__ g, const float* __restrict__ b,
                       float* __restrict__ out, unsigned short* __restrict__ oh,
                       unsigned short* __restrict__ ol, int M)
{
    int gw = (int)((blockIdx.x * (size_t)blockDim.x + threadIdx.x) >> 5);
    int lane = threadIdx.x & 31;
    if (gw >= M) return;
    const float* r1 = x1 + (size_t)gw * ld1;
    const float* r2 = nullptr;
    if (x2mode == 1) r2 = x2 + (size_t)gw * 256;
    else if (x2mode == 2) {
        int c = gw & 3, p = (gw >> 2) & 63, s = (gw >> 8) & 31, bb = gw >> 13;
        int sp = s + c - 3;
        if (sp >= 0) r2 = x2 + (size_t)((bb * 32 + sp) * 64 + p) * 256;
    }
    float v[8], sum = 0.0f;
#pragma unroll
    for (int i = 0; i < 8; i++) {
        float t = r1[lane + i * 32];
        if (r2) t += r2[lane + i * 32];
        v[i] = t; sum += t;
    }
#pragma unroll
    for (int o = 16; o; o >>= 1) sum += __shfl_xor_sync(0xffffffffu, sum, o);
    float mean = sum * (1.0f / 256.0f), var = 0.0f;
#pragma unroll
    for (int i = 0; i < 8; i++) { float d = v[i] - mean; var += d * d; }
#pragma unroll
    for (int o = 16; o; o >>= 1) var += __shfl_xor_sync(0xffffffffu, var, o);
    float rstd = rsqrtf(var * (1.0f / 256.0f) + 1e-5f);
#pragma unroll
    for (int i = 0; i < 8; i++) {
        int d = lane + i * 32;
        float y = (v[i] - mean) * rstd * g[d] + b[d];
        size_t o2 = (size_t)gw * 256 + d;
        if (out) out[o2] = y;
        if (oh) wr_hl(oh, ol, o2, y);
    }
}

// layer-0 ctx attn: qkv of unique tokens, window gather, bias for pad rows
__global__ void ctx_attn0(const float* __restrict__ qkvt, const float* __restrict__ qb,
                          unsigned short* __restrict__ oh, unsigned short* __restrict__ ol)
{
    int gw = (int)((blockIdx.x * (size_t)blockDim.x + threadIdx.x) >> 5);
    int lane = threadIdx.x & 31;
    int seq = gw >> 2, h = gw & 3;
    if (seq >= 16384) return;
    int b = seq >> 11, s = (seq >> 6) & 31, p = seq & 63;
    float q[4][2], k[4][2], v[4][2];
#pragma unroll
    for (int c = 0; c < 4; c++) {
        int sp = s + c - 3;
        const float* row = (sp >= 0)
            ? qkvt + (size_t)((b * 32 + sp) * 64 + p) * 768 + h * 64 : nullptr;
        if (row) {
            q[c][0] = row[lane];       q[c][1] = row[lane + 32];
            k[c][0] = row[256 + lane]; k[c][1] = row[256 + lane + 32];
            v[c][0] = row[512 + lane]; v[c][1] = row[512 + lane + 32];
        } else {
            q[c][0] = qb[h * 64 + lane];       q[c][1] = qb[h * 64 + lane + 32];
            k[c][0] = qb[256 + h * 64 + lane]; k[c][1] = qb[256 + h * 64 + lane + 32];
            v[c][0] = qb[512 + h * 64 + lane]; v[c][1] = qb[512 + h * 64 + lane + 32];
        }
    }
    float pm[4][4];
#pragma unroll
    for (int i = 0; i < 4; i++) {
#pragma unroll
        for (int j = 0; j < 4; j++) {
            float t = q[i][0] * k[j][0] + q[i][1] * k[j][1];
#pragma unroll
            for (int o = 16; o; o >>= 1) t += __shfl_xor_sync(0xffffffffu, t, o);
            pm[i][j] = t * 0.125f;
        }
        float mx = fmaxf(fmaxf(pm[i][0], pm[i][1]), fmaxf(pm[i][2], pm[i][3]));
        float e0 = expf(pm[i][0] - mx), e1 = expf(pm[i][1] - mx);
        float e2 = expf(pm[i][2] - mx), e3 = expf(pm[i][3] - mx);
        float inv = 1.0f / (e0 + e1 + e2 + e3);
        pm[i][0] = e0 * inv; pm[i][1] = e1 * inv; pm[i][2] = e2 * inv; pm[i][3] = e3 * inv;
    }
#pragma unroll
    for (int i = 0; i < 4; i++) {
        float o0 = pm[i][0] * v[0][0] + pm[i][1] * v[1][0] + pm[i][2] * v[2][0] + pm[i][3] * v[3][0];
        float o1 = pm[i][0] * v[0][1] + pm[i][1] * v[1][1] + pm[i][2] * v[2][1] + pm[i][3] * v[3][1];
        size_t row = (size_t)seq * 4 + i;
        wr_hl(oh, ol, row * 256 + h * 64 + lane, o0);
        wr_hl(oh, ol, row * 256 + h * 64 + lane + 32, o1);
    }
}

// layer-1 ctx attn: separate Q (last pos only) and KV buffers
__global__ void ctx_attn1(const float* __restrict__ qbuf, const float* __restrict__ kv,
                          unsigned short* __restrict__ oh, unsigned short* __restrict__ ol)
{
    int gw = (int)((blockIdx.x * (size_t)blockDim.x + threadIdx.x) >> 5);
    int lane = threadIdx.x & 31;
    int seq = gw >> 2, h = gw & 3;
    if (seq >= 16384) return;
    float q0 = qbuf[(size_t)seq * 256 + h * 64 + lane];
    float q1 = qbuf[(size_t)seq * 256 + h * 64 + lane + 32];
    float k[4][2], v[4][2], pr[4];
#pragma unroll
    for (int c = 0; c < 4; c++) {
        const float* base = kv + (size_t)(seq * 4 + c) * 512 + h * 64;
        k[c][0] = base[lane];       k[c][1] = base[lane + 32];
        v[c][0] = base[256 + lane]; v[c][1] = base[256 + lane + 32];
    }
#pragma unroll
    for (int j = 0; j < 4; j++) {
        float t = q0 * k[j][0] + q1 * k[j][1];
#pragma unroll
        for (int o = 16; o; o >>= 1) t += __shfl_xor_sync(0xffffffffu, t, o);
        pr[j] = t * 0.125f;
    }
    float mx = fmaxf(fmaxf(pr[0], pr[1]), fmaxf(pr[2], pr[3]));
    float e0 = expf(pr[0] - mx), e1 = expf(pr[1] - mx), e2 = expf(pr[2] - mx), e3 = expf(pr[3] - mx);
    float inv = 1.0f / (e0 + e1 + e2 + e3);
    pr[0] = e0 * inv; pr[1] = e1 * inv; pr[2] = e2 * inv; pr[3] = e3 * inv;
    float o0 = pr[0] * v[0][0] + pr[1] * v[1][0] + pr[2] * v[2][0] + pr[3] * v[3][0];
    float o1 = pr[0] * v[0][1] + pr[1] * v[1][1] + pr[2] * v[2][1] + pr[3] * v[3][1];
    wr_hl(oh, ol, (size_t)seq * 256 + h * 64 + lane, o0);
    wr_hl(oh, ol, (size_t)seq * 256 + h * 64 + lane + 32, o1);
}

// ---------------- VQ / losses ----------------
__global__ void cb_norms(const float* __restrict__ cb, float* __restrict__ cn)
{
    int gw = (int)((blockIdx.x * (size_t)blockDim.x + threadIdx.x) >> 5);
    int lane = threadIdx.x & 31;
    if (gw >= 1024) return;
    const float* r = cb + (size_t)gw * 256;
    float s = 0.0f;
#pragma unroll
    for (int i = 0; i < 8; i++) { float v = r[lane + i * 32]; s += v * v; }
#pragma unroll
    for (int o = 16; o; o >>= 1) s += __shfl_xor_sync(0xffffffffu, s, o);
    if (!lane) cn[gw] = s;
}

__global__ void vq_argmin(const float* __restrict__ x, const float* __restrict__ scores,
                          const float* __restrict__ cn, int* __restrict__ idx)
{
    int gw = (int)((blockIdx.x * (size_t)blockDim.x + threadIdx.x) >> 5);
    int lane = threadIdx.x & 31;
    if (gw >= 16384) return;
    const float* xr = x + (size_t)gw * 256;
    float xx = 0.0f;
#pragma unroll
    for (int i = 0; i < 8; i++) { float v = xr[lane + i * 32]; xx += v * v; }
#pragma unroll
    for (int o = 16; o; o >>= 1) xx += __shfl_xor_sync(0xffffffffu, xx, o);
    const float* sr = scores + (size_t)gw * 1024;
    float best = 3.4e38f; int bi = 0x7fffffff;
    for (int j = lane; j < 1024; j += 32) {
        float d = (xx - 2.0f * sr[j]) + cn[j];
        if (d < best || (d == best && j < bi)) { best = d; bi = j; }
    }
#pragma unroll
    for (int o = 16; o; o >>= 1) {
        float ob = __shfl_xor_sync(0xffffffffu, best, o);
        int   oi = __shfl_xor_sync(0xffffffffu, bi, o);
        if (ob < best || (ob == best && oi < bi)) { best = ob; bi = oi; }
    }
    if (!lane) idx[gw] = bi;
}

__global__ void mse_partial(const float* __restrict__ x, const float* __restrict__ cb,
                            const int* __restrict__ idx, float* __restrict__ red)
{
    __shared__ float sm[256];
    float s = 0.0f;
    size_t stride = (size_t)gridDim.x * blockDim.x;
    for (size_t i = (size_t)blockIdx.x * blockDim.x + threadIdx.x;
         i < (size_t)16384 * 256; i += stride) {
        int row = (int)(i >> 8), d = (int)(i & 255);
        float diff = x[i] - cb[(size_t)idx[row] * 256 + d];
        s += diff * diff;
    }
    sm[threadIdx.x] = s; __syncthreads();
    for (int o = 128; o; o >>= 1) {
        if ((int)threadIdx.x < o) sm[threadIdx.x] += sm[threadIdx.x + o];
        __syncthreads();
    }
    if (!threadIdx.x) red[blockIdx.x] = sm[0];
}

__global__ void mse_final(const float* __restrict__ red, float* __restrict__ out)
{
    __shared__ float sm[256];
    sm[threadIdx.x] = red[threadIdx.x]; __syncthreads();
    for (int o = 128; o; o >>= 1) {
        if ((int)threadIdx.x < o) sm[threadIdx.x] += sm[threadIdx.x + o];
        __syncthreads();
    }
    if (!threadIdx.x) {
        float mse = sm[0] / 4194304.0f;
        out[1064960] = 0.25f * mse;
        out[1064961] = mse;
        out[1064962] = 1.25f * mse;
    }
}

__global__ void idx_write(const int* __restrict__ idx, float* __restrict__ out)
{
    int i = blockIdx.x * blockDim.x + threadIdx.x;
    if (i < 16384) out[1048576 + i] = (float)idx[i];
}

// ---------------- host ----------------
static inline void* symp(const void* s)
{
    void* p = nullptr;
    cudaGetSymbolAddress(&p, s);
    return p;
}

extern "C" void kernel_launch(void* const* d_in, const int* in_sizes, int n_in,
                              void* d_out, int out_size)
{
    (void)in_sizes; (void)n_in; (void)out_size;
    const float* obs      = (const float*)d_in[0];
    const float* patch_w  = (const float*)d_in[2];
    const float* patch_b  = (const float*)d_in[3];
    const float* pos_emb  = (const float*)d_in[4];
    const float* sa_qkv_w = (const float*)d_in[5];
    const float* sa_qkv_b = (const float*)d_in[6];
    const float* sa_out_w = (const float*)d_in[7];
    const float* sa_out_b = (const float*)d_in[8];
    const float* sa_ln_g  = (const float*)d_in[9];
    const float* sa_ln_b  = (const float*)d_in[10];
    const float* cqkv_w   = (const float*)d_in[11];
    const float* cqkv_b   = (const float*)d_in[12];
    const float* cout_w   = (const float*)d_in[13];
    const float* cout_b   = (const float*)d_in[14];
    const float* cff1_w   = (const float*)d_in[15];
    const float* cff1_b   = (const float*)d_in[16];
    const float* cff2_w   = (const float*)d_in[17];
    const float* cff2_b   = (const float*)d_in[18];
    const float* cln1_g   = (const float*)d_in[19];
    const float* cln1_b   = (const float*)d_in[20];
    const float* cln2_g   = (const float*)d_in[21];
    const float* cln2_b   = (const float*)d_in[22];
    const float* delta_w  = (const float*)d_in[23];
    const float* delta_b  = (const float*)d_in[24];
    const float* codebook = (const float*)d_in[25];
    const float* dec_w1   = (const float*)d_in[26];
    const float* dec_b1   = (const float*)d_in[27];
    const float* dec_w2   = (const float*)d_in[28];
    const float* dec_b2   = (const float*)d_in[29];
    const float* dec_w3   = (const float*)d_in[30];
    const float* dec_b3   = (const float*)d_in[31];
    float* out = (float*)d_out;

    float* obsproj = (float*)symp(g_obsproj);
    float* x0      = (float*)symp(g_x0);
    float* qkv     = (float*)symp(g_qkv);
    float* kvbuf   = qkv + (size_t)16384 * 768;
    float* proj    = (float*)symp(g_proj);
    float* tok     = (float*)symp(g_tok);
    float* xctx    = (float*)symp(g_xctx);
    float* hid     = (float*)symp(g_hid);
    float* xlast   = (float*)symp(g_xlast);
    float* cur     = (float*)symp(g_cur);
    float* ctxtok  = (float*)symp(g_ctxtok);
    float* cn      = (float*)symp(g_cn);
    float* red     = (float*)symp(g_red);
    int*   vidx    = (int*)symp(g_idx);
    unsigned short* x0h = (unsigned short*)symp(g_x0h);
    unsigned short* x0l = (unsigned short*)symp(g_x0l);
    unsigned short* tkh = (unsigned short*)symp(g_tkh);
    unsigned short* tkl = (unsigned short*)symp(g_tkl);
    unsigned short* ath = (unsigned short*)symp(g_ath);
    unsigned short* atl = (unsigned short*)symp(g_atl);
    unsigned short* xh  = (unsigned short*)symp(g_xh);
    unsigned short* xl  = (unsigned short*)symp(g_xl);
    unsigned short* hh  = (unsigned short*)symp(g_hh);
    unsigned short* hl  = (unsigned short*)symp(g_hl);
    unsigned short* xlh = (unsigned short*)symp(g_xlh);
    unsigned short* xll = (unsigned short*)symp(g_xll);
    unsigned short* cth = (unsigned short*)symp(g_cth);
    unsigned short* ctl = (unsigned short*)symp(g_ctl);
    unsigned short* wsh = (unsigned short*)symp(g_wsh);
    unsigned short* wsl = (unsigned short*)symp(g_wsl);
    unsigned short* wh  = (unsigned short*)symp(g_wh);
    unsigned short* wl  = (unsigned short*)symp(g_wl);
    unsigned short* fh  = (unsigned short*)symp(g_fh);
    unsigned short* fl  = (unsigned short*)symp(g_fl);

    const int SM128 = 2 * (2 * 128 * 40 + 2 * 128 * 40) * 2;
    const int SM64  = 2 * (2 * 128 * 40 + 2 * 64 * 40) * 2;
    cudaFuncSetAttribute(gemm_mma<128, 3, false>, cudaFuncAttributeMaxDynamicSharedMemorySize, SM128);
    cudaFuncSetAttribute(gemm_mma<128, 2, true>,  cudaFuncAttributeMaxDynamicSharedMemorySize, SM128);
    cudaFuncSetAttribute(gemm_mma<64, 2, true>,   cudaFuncAttributeMaxDynamicSharedMemorySize, SM64);

    const int T = 256;

    // batched weight conversions (bf16 pool, fp16 pool)
    {
        ConvTab tb = {};
        const float* srcs[11] = { sa_qkv_w, sa_out_w, cqkv_w, cqkv_w + 196608,
                                  cout_w, cout_w + 65536, cff1_w, cff1_w + 262144,
                                  cff2_w, cff2_w + 262144, codebook };
        long offs[11] = { OFF_SAQKV, OFF_SAOUT, OFF_CQKV0, OFF_CQKV1, OFF_COUT0,
                          OFF_COUT1, OFF_FF1_0, OFF_FF1_1, OFF_FF2_0, OFF_FF2_1, OFF_CB };
        long ns[11] = { 196608, 65536, 196608, 196608, 65536, 65536,
                        262144, 262144, 262144, 262144, 262144 };
        long cum = 0;
        for (int i = 0; i < 11; i++) {
            tb.s[i].src = srcs[i]; tb.s[i].off = offs[i];
            tb.cum[i] = cum; cum += ns[i];
        }
        tb.cum[11] = cum; tb.cnt = 11;
        conv_batch<<<(int)((cum + 255) / 256), 256>>>(tb, wh, wl, 0, cum);

        ConvTab tf = {};
        const float* fsrcs[4] = { dec_w1, dec_w2, dec_w3, codebook };
        long foffs[4] = { OFF_FD1, OFF_FD2, OFF_FD3, OFF_FCB };
        long fns[4] = { 262144, 1048576, 65536, 262144 };
        cum = 0;
        for (int i = 0; i < 4; i++) {
            tf.s[i].src = fsrcs[i]; tf.s[i].off = foffs[i];
            tf.cum[i] = cum; cum += fns[i];
        }
        tf.cum[4] = cum; tf.cnt = 4;
        conv_batch<<<(int)((cum + 255) / 256), 256>>>(tf, fh, fl, 1, cum);
    }

    auto G = [&](const unsigned short* Ah, const unsigned short* Al, int woff,
                 const float* bias, float* C, unsigned short* Chi, unsigned short* Clo,
                 int M, int N, int K, int relu, const int* Arows, int amul, int aadd) {
        gemm_mma<128, 3, false><<<dim3(N / 128, M / 128), 256, SM128>>>(
            Ah, Al, wh + woff, wl + woff, bias, C, Chi, Clo, N, K, relu, Arows, amul, aadd);
    };
    auto Gf = [&](const unsigned short* Ah, const unsigned short* Al, int woff,
                  const float* bias, unsigned short* Chi, unsigned short* Clo,
                  int M, int N, int K, int relu, const int* Arows) {
        gemm_mma<128, 2, true><<<dim3(N / 128, M / 128), 256, SM128>>>(
            Ah, Al, fh + woff, fl + woff, bias, nullptr, Chi, Clo, N, K, relu, Arows, 1, 0);
    };

    // 1) patch projection + positional embed
    gemm_nt<<<dim3(4, 4), T>>>(obs, patch_w, patch_b, obsproj, 256, 256, 64);
    expand_tok<<<16384, T>>>(obsproj, pos_emb, x0, x0h, x0l);

    // 2) self-attention block
    G(x0h, x0l, OFF_SAQKV, sa_qkv_b, qkv, nullptr, nullptr, 16384, 768, 256, 0, nullptr, 1, 0);
    sa_attn<<<dim3(256, 4), T>>>(qkv, ath, atl);
    G(ath, atl, OFF_SAOUT, sa_out_b, proj, nullptr, nullptr, 16384, 256, 256, 0, nullptr, 1, 0);
    ln_res<<<2048, T>>>(proj, 256, x0, 1, sa_ln_g, sa_ln_b, tok, tkh, tkl, 16384);

    // 3) context layer 0
    G(tkh, tkl, OFF_CQKV0, cqkv_b, qkv, nullptr, nullptr, 16384, 768, 256, 0, nullptr, 1, 0);
    ctx_attn0<<<8192, T>>>(qkv, cqkv_b, ath, atl);
    G(ath, atl, OFF_COUT0, cout_b, proj, nullptr, nullptr, 65536, 256, 256, 0, nullptr, 1, 0);
    ln_res<<<8192, T>>>(proj, 256, tok, 2, cln1_g, cln1_b, xctx, xh, xl, 65536);
    G(xh, xl, OFF_FF1_0, cff1_b, nullptr, hh, hl, 65536, 1024, 256, 1, nullptr, 1, 0);
    G(hh, hl, OFF_FF2_0, cff2_b, proj, nullptr, nullptr, 65536, 256, 1024, 0, nullptr, 1, 0);
    ln_res<<<8192, T>>>(xctx, 256, proj, 1, cln2_g, cln2_b, xctx, xh, xl, 65536);

    // 4) context layer 1 (KV all rows, Q at last position)
    G(xh, xl, OFF_CKV1, cqkv_b + 768 + 256, kvbuf, nullptr, nullptr, 65536, 512, 256, 0, nullptr, 1, 0);
    G(xh, xl, OFF_CQKV1, cqkv_b + 768, x0, nullptr, nullptr, 16384, 256, 256, 0, nullptr, 4, 3);
    ctx_attn1<<<8192, T>>>(x0, kvbuf, ath, atl);
    G(ath, atl, OFF_COUT1, cout_b + 256, proj, nullptr, nullptr, 16384, 256, 256, 0, nullptr, 1, 0);
    ln_res<<<2048, T>>>(xctx + 768, 1024, proj, 1, cln1_g + 256, cln1_b + 256, xlast, xlh, xll, 16384);
    G(xlh, xll, OFF_FF1_1, cff1_b + 1024, nullptr, hh, hl, 16384, 1024, 256, 1, nullptr, 1, 0);
    G(hh, hl, OFF_FF2_1, cff2_b + 256, proj, nullptr, nullptr, 16384, 256, 1024, 0, nullptr, 1, 0);
    // cur in fp32 AND hi/lo (xlh/xll reusable now)
    ln_res<<<2048, T>>>(xlast, 256, proj, 1, cln2_g + 256, cln2_b + 256, cur, xlh, xll, 16384);

    // 5) delta scan: Acc = cur@(W1+W2)^T + b (one MMA gemm), then 31 half-K steps
    wsum_make<<<256, T>>>(delta_w, obsproj);               // obsproj dead: reuse as W1+W2
    conv_hl<<<256, T>>>(obsproj, wsh, wsl, 65536);
    gemm_mma<128, 3, false><<<dim3(2, 128), 256, SM128>>>(
        xlh, xll, wsh, wsl, delta_b, hid, nullptr, nullptr, 256, 256, 0, nullptr, 1, 0);
    copy_out0<<<512, T>>>(cur, ctxtok);
    for (int s = 1; s < 32; s++)
        gemm_scan2<<<dim3(4, 8), T>>>(hid, delta_w + 256, ctxtok, s);
    conv_hl<<<16384, T>>>(ctxtok, cth, ctl, 16384 * 256);

    // 6) VQ
    cb_norms<<<128, T>>>(codebook, cn);
    G(cth, ctl, OFF_CB, nullptr, hid, nullptr, nullptr, 16384, 1024, 256, 0, nullptr, 1, 0);
    vq_argmin<<<2048, T>>>(ctxtok, hid, cn, vidx);

    // 7) losses + idx
    mse_partial<<<256, T>>>(ctxtok, codebook, vidx, red);
    mse_final<<<1, T>>>(red, out);
    idx_write<<<64, T>>>(vidx, out);

    // 8) decoder (fp16 hi/lo, 2-MMA split)
    Gf(fh + OFF_FCB, fl + OFF_FCB, OFF_FD1, dec_b1, ath, atl, 16384, 1024, 256, 1, vidx);
    Gf(ath, atl, OFF_FD2, dec_b2, xh, xl, 16384, 1024, 1024, 1, nullptr);
    gemm_mma<64, 2, true><<<dim3(1, 128), 256, SM64>>>(
        xh, xl, fh + OFF_FD3, fl + OFF_FD3, dec_b3, out, nullptr, nullptr,
        64, 1024, 0, nullptr, 1, 0);
}